// round 10
// baseline (speedup 1.0000x reference)
#include <cuda_runtime.h>
#include <cuda_bf16.h>
#include <cstdint>
#include <math.h>

#define BB 4
#define SS 1024
#define EE 768
#define HH 12
#define DD 64
#define MT (BB*SS)
#define SCALING 0.125f

// ---------------- device scratch (allocation-free rule) ----------------
__device__ __nv_bfloat16 g_Qhi[BB*HH*SS*DD], g_Qlo[BB*HH*SS*DD];
__device__ __nv_bfloat16 g_Khi[BB*HH*SS*DD], g_Klo[BB*HH*SS*DD];
__device__ __nv_bfloat16 g_Vhi[BB*HH*SS*DD], g_Vlo[BB*HH*SS*DD];
__device__ __nv_bfloat16 g_Xhi[MT*EE],  g_Xlo[MT*EE];
__device__ __nv_bfloat16 g_Whi[4*EE*EE], g_Wlo[4*EE*EE];
__device__ __nv_bfloat16 g_AOhi[MT*EE], g_AOlo[MT*EE];

__device__ __forceinline__ uint32_t smem_u32(const void* p) {
    uint32_t a;
    asm("{ .reg .u64 t; cvta.to.shared.u64 t, %1; cvt.u32.u64 %0, t; }"
        : "=r"(a) : "l"(p));
    return a;
}

#define LDSM4(r, addr) \
    asm volatile("ldmatrix.sync.aligned.m8n8.x4.shared.b16 {%0,%1,%2,%3}, [%4];" \
        : "=r"((r)[0]), "=r"((r)[1]), "=r"((r)[2]), "=r"((r)[3]) : "r"(addr))
#define LDSM4T(r, addr) \
    asm volatile("ldmatrix.sync.aligned.m8n8.x4.trans.shared.b16 {%0,%1,%2,%3}, [%4];" \
        : "=r"((r)[0]), "=r"((r)[1]), "=r"((r)[2]), "=r"((r)[3]) : "r"(addr))

#define MMA_BF16(d, a, b0v, b1v) \
    asm volatile("mma.sync.aligned.m16n8k16.row.col.f32.bf16.bf16.f32 " \
        "{%0,%1,%2,%3}, {%4,%5,%6,%7}, {%8,%9}, {%0,%1,%2,%3};" \
        : "+f"((d)[0]), "+f"((d)[1]), "+f"((d)[2]), "+f"((d)[3]) \
        : "r"((a)[0]), "r"((a)[1]), "r"((a)[2]), "r"((a)[3]), "r"(b0v), "r"(b1v))

#define CP_ASYNC16(smem, gmem) \
    asm volatile("cp.async.cg.shared.global [%0], [%1], 16;" :: "r"(smem), "l"(gmem))
#define CP_COMMIT()  asm volatile("cp.async.commit_group;" ::: "memory")
#define CP_WAIT0()   asm volatile("cp.async.wait_group 0;" ::: "memory")
#define CP_WAIT1()   asm volatile("cp.async.wait_group 1;" ::: "memory")

// pack 2 fp32 -> bf16x2 hi + bf16x2 lo (3-split residual), cvt.bf16x2 fast path
__device__ __forceinline__ void splitpack(float x, float y, uint32_t& hi, uint32_t& lo) {
    asm("cvt.rn.bf16x2.f32 %0, %1, %2;" : "=r"(hi) : "f"(y), "f"(x));
    float hx = __uint_as_float(hi << 16);
    float hy = __uint_as_float(hi & 0xffff0000u);
    float lx = x - hx, ly = y - hy;
    asm("cvt.rn.bf16x2.f32 %0, %1, %2;" : "=r"(lo) : "f"(ly), "f"(lx));
}

// ---------------------------------------------------------------------------
// merged fp32 -> (bf16 hi, lo) split. 8 float4 per thread (MLP=8).
// ---------------------------------------------------------------------------
__global__ void __launch_bounds__(256) split_all_kernel(
    const float* __restrict__ X,
    const float* __restrict__ qw, const float* __restrict__ kw,
    const float* __restrict__ vw, const float* __restrict__ ow)
{
    const int bid = blockIdx.x;
    const float* src;
    __nv_bfloat16 *dhi, *dlo;
    size_t off;
    if (bid < 384) {
        src = X; dhi = g_Xhi; dlo = g_Xlo;
        off = (size_t)bid * 8192;
    } else {
        int r = bid - 384;
        int slot = r / 72, rb = r % 72;
        src = (slot == 0) ? qw : (slot == 1) ? kw : (slot == 2) ? vw : ow;
        dhi = g_Whi + (size_t)slot * EE * EE;
        dlo = g_Wlo + (size_t)slot * EE * EE;
        off = (size_t)rb * 8192;
    }
    float4 v[8];
    #pragma unroll
    for (int u = 0; u < 8; u++)
        v[u] = *(const float4*)(src + off + u*1024 + threadIdx.x*4);
    #pragma unroll
    for (int u = 0; u < 8; u++) {
        size_t i = off + u*1024 + threadIdx.x*4;
        float xs[4] = {v[u].x, v[u].y, v[u].z, v[u].w};
        #pragma unroll
        for (int j = 0; j < 4; j++) {
            __nv_bfloat16 hv = __float2bfloat16(xs[j]);
            dhi[i+j] = hv;
            dlo[i+j] = __float2bfloat16(xs[j] - __bfloat162float(hv));
        }
    }
}

// ---------------------------------------------------------------------------
// HMMA GEMM: D = A(M,K) @ W(N,K)^T via 3x bf16-split mma.sync, fp32 accum.
// CTA 128x128, 8 warps (2x4), warp tile 64x32, BK=32, 3-stage cp.async.
// 1 CTA/SM, 255-reg budget: ALL B frags for the stage preloaded (64 regs),
// A frags double-buffered across the t loop (32 regs) -> every LDSM's
// consumers are >=24 MMAs downstream; smem latency fully hidden.
// ---------------------------------------------------------------------------
#define NS (EE/32)   // 24 K-stages
__global__ void __launch_bounds__(256, 1) gemm_mma_kernel(
    const float* __restrict__ b0p, const float* __restrict__ b1p,
    const float* __restrict__ b2p, float* __restrict__ outp,
    int wslot0, int is_qkv)
{
    extern __shared__ char dsm[];
    const uint32_t sbase = smem_u32(dsm);

    const int tid = threadIdx.x;
    const int wid = tid >> 5, lane = tid & 31;
    const int warp_m = wid & 1, warp_n = wid >> 1;
    const int m0w = warp_m * 64, n0w = warp_n * 32;

    const int z = is_qkv ? blockIdx.z : 0;
    const size_t woff = (size_t)(wslot0 + z) * EE * EE;
    const float* bias = (z == 0) ? b0p : (z == 1) ? b1p : b2p;
    const float scale = (is_qkv && z == 0) ? SCALING : 1.0f;
    __nv_bfloat16* outHi = (z == 0) ? g_Qhi : (z == 1) ? g_Khi : g_Vhi;
    __nv_bfloat16* outLo = (z == 0) ? g_Qlo : (z == 1) ? g_Klo : g_Vlo;

    const int n0 = blockIdx.x * 128;
    const int m0 = blockIdx.y * 128;

    const __nv_bfloat16* s0 = (is_qkv ? g_Xhi : g_AOhi) + (size_t)m0 * EE;
    const __nv_bfloat16* s1 = (is_qkv ? g_Xlo : g_AOlo) + (size_t)m0 * EE;
    const __nv_bfloat16* s2 = g_Whi + woff + (size_t)n0 * EE;
    const __nv_bfloat16* s3 = g_Wlo + woff + (size_t)n0 * EE;

    const int lrow = tid >> 2;
    const int lch  = tid & 3;
    auto stage_load = [&](int k0, int stg) {
        uint32_t sb = sbase + (uint32_t)stg * 32768u;
        #pragma unroll
        for (int t = 0; t < 4; t++) {
            const __nv_bfloat16* sp = (t==0?s0:t==1?s1:t==2?s2:s3) + k0 + lch*8;
            uint32_t tb = sb + (uint32_t)t * 8192u;
            #pragma unroll
            for (int j = 0; j < 2; j++) {
                int row = lrow + j*64;
                CP_ASYNC16(tb + row*64 + ((lch ^ ((row >> 1) & 3)) << 4),
                           sp + (size_t)row * EE);
            }
        }
        CP_COMMIT();
    };

    const int l7 = lane & 7;
    const int arow_sw = (lane >> 1) & 3;
    const int brow7 = l7 + ((lane >> 4) << 3);
    const int brow_sw = (brow7 >> 1) & 3;
    uint32_t aoff[4], boff[2];
    #pragma unroll
    for (int t = 0; t < 4; t++)
        aoff[t] = (uint32_t)(m0w + t*16 + (lane & 15)) * 64u;
    #pragma unroll
    for (int p = 0; p < 2; p++)
        boff[p] = (uint32_t)(n0w + p*16 + brow7) * 64u;
    const int achk = lane >> 4;
    const int bchk = (lane >> 3) & 1;

    float acc[4][4][4] = {};

    stage_load(0, 0);
    stage_load(32, 1);

    #pragma unroll 1
    for (int s = 0; s < NS; s++) {
        if (s == NS - 1) { CP_WAIT0(); } else { CP_WAIT1(); }
        __syncthreads();
        if (s + 2 < NS) stage_load((s + 2) * 32, (s + 2) % 3);

        const uint32_t stg = sbase + (uint32_t)(s % 3) * 32768u;
        const uint32_t Ahi = stg, Alo = stg + 8192u;
        const uint32_t Bhi = stg + 16384u, Blo = stg + 24576u;

        // preload ALL B fragments for both k-steps of this stage (64 regs)
        uint32_t Bh[2][2][4], Bl[2][2][4];   // [ks][p]
        #pragma unroll
        for (int ks = 0; ks < 2; ks++) {
            const uint32_t bsw = (uint32_t)((2*ks + bchk) ^ brow_sw) << 4;
            #pragma unroll
            for (int p = 0; p < 2; p++) {
                LDSM4(Bh[ks][p], Bhi + boff[p] + bsw);
                LDSM4(Bl[ks][p], Blo + boff[p] + bsw);
            }
        }
        // A fragments double-buffered over t (32 regs)
        uint32_t Ah[2][2][4], Al[2][2][4];   // [buf][ks]
        #pragma unroll
        for (int ks = 0; ks < 2; ks++) {
            const uint32_t asw = (uint32_t)((2*ks + achk) ^ arow_sw) << 4;
            LDSM4(Ah[0][ks], Ahi + aoff[0] + asw);
            LDSM4(Al[0][ks], Alo + aoff[0] + asw);
        }
        #pragma unroll
        for (int t = 0; t < 4; t++) {
            const int cur = t & 1;
            if (t < 3) {
                const int nxt = cur ^ 1;
                #pragma unroll
                for (int ks = 0; ks < 2; ks++) {
                    const uint32_t asw = (uint32_t)((2*ks + achk) ^ arow_sw) << 4;
                    LDSM4(Ah[nxt][ks], Ahi + aoff[t+1] + asw);
                    LDSM4(Al[nxt][ks], Alo + aoff[t+1] + asw);
                }
            }
            #pragma unroll
            for (int ks = 0; ks < 2; ks++) {
                #pragma unroll
                for (int n = 0; n < 4; n++) {
                    const int p = n >> 1, q = (n & 1) * 2;
                    MMA_BF16(acc[t][n], Ah[cur][ks], Bh[ks][p][q], Bh[ks][p][q+1]);
                }
                #pragma unroll
                for (int n = 0; n < 4; n++) {
                    const int p = n >> 1, q = (n & 1) * 2;
                    MMA_BF16(acc[t][n], Ah[cur][ks], Bl[ks][p][q], Bl[ks][p][q+1]);
                }
                #pragma unroll
                for (int n = 0; n < 4; n++) {
                    const int p = n >> 1, q = (n & 1) * 2;
                    MMA_BF16(acc[t][n], Al[cur][ks], Bh[ks][p][q], Bh[ks][p][q+1]);
                }
            }
        }
    }

    // epilogue
    const int rl = lane >> 2, cl2 = (lane & 3) * 2;
    #pragma unroll
    for (int t = 0; t < 4; t++)
        #pragma unroll
        for (int n = 0; n < 4; n++) {
            const int col = n0 + n0w + n*8 + cl2;
            #pragma unroll
            for (int half = 0; half < 2; half++) {
                const int row = m0 + m0w + t*16 + rl + half*8;
                float ox = (acc[t][n][half*2+0] + bias[col+0]) * scale;
                float oy = (acc[t][n][half*2+1] + bias[col+1]) * scale;
                if (is_qkv) {
                    const int hh = col >> 6, d0 = col & 63;
                    const int bb_ = row >> 10, ss_ = row & 1023;
                    size_t idx = ((size_t)((bb_*HH + hh)*SS + ss_))*DD + d0;
                    uint32_t hi, lo;
                    splitpack(ox, oy, hi, lo);
                    *(uint32_t*)(outHi + idx) = hi;
                    *(uint32_t*)(outLo + idx) = lo;
                } else {
                    float2 o; o.x = ox; o.y = oy;
                    *(float2*)(outp + (size_t)row * EE + col) = o;
                }
            }
        }
}

// ---------------------------------------------------------------------------
// Flash attention on mma.sync bf16 (3-split). CTA = 128 Q rows x (b,h).
// 8 warps, warp = m16 x n64. K/V chunks of 64 rows, double-buffered cp.async.
// ---------------------------------------------------------------------------
__global__ void __launch_bounds__(256, 2) attn_mma_kernel(
    const int* __restrict__ pos_row, const int* __restrict__ pos_col,
    const float* __restrict__ rel_table)
{
    extern __shared__ char dsm[];
    const uint32_t sbase = smem_u32(dsm);
    const uint32_t sQhi = sbase, sQlo = sbase + 16384u;
    int* pk = (int*)(dsm + 98304);

    const int tid = threadIdx.x;
    const int wid = tid >> 5, lane = tid & 31;
    const int l7 = lane & 7;
    const int rl = lane >> 2, cl2 = (lane & 3) * 2;
    const int achk = lane >> 4;
    const int bchk = (lane >> 3) & 1;

    const int q0 = blockIdx.x * 128;
    const int h = blockIdx.y, b = blockIdx.z;
    const size_t hb = (size_t)(b*HH + h) * SS * DD;

    #pragma unroll
    for (int i = 0; i < 4; i++) {
        int s = tid + i*256;
        pk[s] = (pos_row[b*SS + s] << 5) | pos_col[b*SS + s];
    }

    {
        const int half = tid >> 7, r = tid & 127;
        const __nv_bfloat16* src = (half ? g_Qlo : g_Qhi) + hb + (size_t)(q0 + r)*DD;
        uint32_t dstrow = (half ? sQlo : sQhi) + (uint32_t)r * 128u;
        #pragma unroll
        for (int ch = 0; ch < 8; ch++)
            CP_ASYNC16(dstrow + ((ch ^ (r & 7)) << 4), src + ch*8);
        CP_COMMIT();
    }

    auto kv_load = [&](int kb, int stg) {
        const int t = tid >> 6, r = tid & 63;
        const __nv_bfloat16* src =
            (t==0 ? g_Khi : t==1 ? g_Klo : t==2 ? g_Vhi : g_Vlo)
            + hb + (size_t)(kb + r)*DD;
        uint32_t dstrow = sbase + 32768u + (uint32_t)stg*32768u
                        + (uint32_t)t*8192u + (uint32_t)r*128u;
        #pragma unroll
        for (int ch = 0; ch < 8; ch++)
            CP_ASYNC16(dstrow + ((ch ^ (r & 7)) << 4), src + ch*8);
        CP_COMMIT();
    };
    kv_load(0, 0);

    CP_WAIT1();
    __syncthreads();

    uint32_t qh[4][4], ql[4][4];
    const uint32_t aq = (uint32_t)(wid*16 + (lane & 15)) * 128u;
    #pragma unroll
    for (int ks = 0; ks < 4; ks++) {
        uint32_t sw = (uint32_t)((2*ks + achk) ^ l7) << 4;
        LDSM4(qh[ks], sQhi + aq + sw);
        LDSM4(ql[ks], sQlo + aq + sw);
    }

    const int rq0 = pk[q0 + wid*16 + rl];
    const int rq1 = pk[q0 + wid*16 + rl + 8];
    const float tb0 = rel_table[0*HH + h];
    const float tb1 = rel_table[1*HH + h];
    const float tb2 = rel_table[2*HH + h];
    const float tb3 = rel_table[3*HH + h];

    float oacc[8][4] = {};
    float m0 = -1e30f, m1 = -1e30f, l0 = 0.f, l1 = 0.f;

    #pragma unroll 1
    for (int kt = 0; kt < SS/64; kt++) {
        CP_WAIT0();
        __syncthreads();
        if (kt + 1 < SS/64) kv_load((kt + 1) * 64, (kt + 1) & 1);

        const uint32_t st  = sbase + 32768u + (uint32_t)(kt & 1) * 32768u;
        const uint32_t Khi = st, Klo = st + 8192u;
        const uint32_t Vhi = st + 16384u, Vlo = st + 24576u;

        float sacc[8][4] = {};
        #pragma unroll
        for (int ks = 0; ks < 4; ks++) {
            const uint32_t bsw = (uint32_t)((2*ks + bchk) ^ l7) << 4;
            #pragma unroll
            for (int p = 0; p < 4; p++) {
                const uint32_t bo =
                    (uint32_t)(p*16 + l7 + ((lane >> 4) << 3)) * 128u + bsw;
                uint32_t Bh[4], Bl[4];
                LDSM4(Bh, Khi + bo);
                LDSM4(Bl, Klo + bo);
                MMA_BF16(sacc[2*p],   qh[ks], Bh[0], Bh[1]);
                MMA_BF16(sacc[2*p+1], qh[ks], Bh[2], Bh[3]);
                MMA_BF16(sacc[2*p],   qh[ks], Bl[0], Bl[1]);
                MMA_BF16(sacc[2*p+1], qh[ks], Bl[2], Bl[3]);
                MMA_BF16(sacc[2*p],   ql[ks], Bh[0], Bh[1]);
                MMA_BF16(sacc[2*p+1], ql[ks], Bh[2], Bh[3]);
            }
        }

        const int kb = kt * 64;
        #pragma unroll
        for (int t = 0; t < 8; t++) {
            int c0 = kb + t*8 + cl2;
            int rk0 = pk[c0], rk1 = pk[c0 + 1];
            int x;
            x = rq0 ^ rk0; sacc[t][0] += (x < 32) ? (((x & 31) == 0) ? tb3 : tb1)
                                                  : (((x & 31) == 0) ? tb2 : tb0);
            x = rq0 ^ rk1; sacc[t][1] += (x < 32) ? (((x & 31) == 0) ? tb3 : tb1)
                                                  : (((x & 31) == 0) ? tb2 : tb0);
            x = rq1 ^ rk0; sacc[t][2] += (x < 32) ? (((x & 31) == 0) ? tb3 : tb1)
                                                  : (((x & 31) == 0) ? tb2 : tb0);
            x = rq1 ^ rk1; sacc[t][3] += (x < 32) ? (((x & 31) == 0) ? tb3 : tb1)
                                                  : (((x & 31) == 0) ? tb2 : tb0);
        }

        float mx0 = sacc[0][0], mx1 = sacc[0][2];
        #pragma unroll
        for (int t = 0; t < 8; t++) {
            mx0 = fmaxf(mx0, fmaxf(sacc[t][0], sacc[t][1]));
            mx1 = fmaxf(mx1, fmaxf(sacc[t][2], sacc[t][3]));
        }
        mx0 = fmaxf(mx0, __shfl_xor_sync(0xffffffffu, mx0, 1));
        mx0 = fmaxf(mx0, __shfl_xor_sync(0xffffffffu, mx0, 2));
        mx1 = fmaxf(mx1, __shfl_xor_sync(0xffffffffu, mx1, 1));
        mx1 = fmaxf(mx1, __shfl_xor_sync(0xffffffffu, mx1, 2));
        float mn0 = fmaxf(m0, mx0), mn1 = fmaxf(m1, mx1);
        float sc0 = __expf(m0 - mn0), sc1 = __expf(m1 - mn1);
        m0 = mn0; m1 = mn1;
        float rs0 = 0.f, rs1 = 0.f;
        #pragma unroll
        for (int t = 0; t < 8; t++) {
            sacc[t][0] = __expf(sacc[t][0] - mn0);
            sacc[t][1] = __expf(sacc[t][1] - mn0);
            sacc[t][2] = __expf(sacc[t][2] - mn1);
            sacc[t][3] = __expf(sacc[t][3] - mn1);
            rs0 += sacc[t][0] + sacc[t][1];
            rs1 += sacc[t][2] + sacc[t][3];
        }
        rs0 += __shfl_xor_sync(0xffffffffu, rs0, 1);
        rs0 += __shfl_xor_sync(0xffffffffu, rs0, 2);
        rs1 += __shfl_xor_sync(0xffffffffu, rs1, 1);
        rs1 += __shfl_xor_sync(0xffffffffu, rs1, 2);
        l0 = l0 * sc0 + rs0;
        l1 = l1 * sc1 + rs1;
        #pragma unroll
        for (int t = 0; t < 8; t++) {
            oacc[t][0] *= sc0; oacc[t][1] *= sc0;
            oacc[t][2] *= sc1; oacc[t][3] *= sc1;
        }

        #pragma unroll
        for (int ks = 0; ks < 4; ks++) {
            uint32_t ph[4], pl[4];
            splitpack(sacc[2*ks][0],   sacc[2*ks][1],   ph[0], pl[0]);
            splitpack(sacc[2*ks][2],   sacc[2*ks][3],   ph[1], pl[1]);
            splitpack(sacc[2*ks+1][0], sacc[2*ks+1][1], ph[2], pl[2]);
            splitpack(sacc[2*ks+1][2], sacc[2*ks+1][3], ph[3], pl[3]);
            const uint32_t vr =
                (uint32_t)(ks*16 + l7 + (((lane >> 3) & 1) << 3)) * 128u;
            #pragma unroll
            for (int p = 0; p < 4; p++) {
                const uint32_t vsw = (uint32_t)((2*p + achk) ^ l7) << 4;
                uint32_t Vh[4], Vl[4];
                LDSM4T(Vh, Vhi + vr + vsw);
                LDSM4T(Vl, Vlo + vr + vsw);
                MMA_BF16(oacc[2*p],   ph, Vh[0], Vh[1]);
                MMA_BF16(oacc[2*p+1], ph, Vh[2], Vh[3]);
                MMA_BF16(oacc[2*p],   ph, Vl[0], Vl[1]);
                MMA_BF16(oacc[2*p+1], ph, Vl[2], Vl[3]);
                MMA_BF16(oacc[2*p],   pl, Vh[0], Vh[1]);
                MMA_BF16(oacc[2*p+1], pl, Vh[2], Vh[3]);
            }
        }
    }

    const float inv0 = 1.0f / l0, inv1 = 1.0f / l1;
    const int qrow0 = q0 + wid*16 + rl;
    #pragma unroll
    for (int t = 0; t < 8; t++) {
        const int e = h*64 + t*8 + cl2;
        size_t i0 = (size_t)(b*SS + qrow0) * EE + e;
        size_t i1 = (size_t)(b*SS + qrow0 + 8) * EE + e;
        uint32_t hi, lo;
        splitpack(oacc[t][0] * inv0, oacc[t][1] * inv0, hi, lo);
        *(uint32_t*)(g_AOhi + i0) = hi;
        *(uint32_t*)(g_AOlo + i0) = lo;
        splitpack(oacc[t][2] * inv1, oacc[t][3] * inv1, hi, lo);
        *(uint32_t*)(g_AOhi + i1) = hi;
        *(uint32_t*)(g_AOlo + i1) = lo;
    }
}

// ---------------------------------------------------------------------------
extern "C" void kernel_launch(void* const* d_in, const int* in_sizes, int n_in,
                              void* d_out, int out_size) {
    const float* X  = (const float*)d_in[0];
    const int*   pr = (const int*)  d_in[1];
    const int*   pc = (const int*)  d_in[2];
    const float* qw = (const float*)d_in[3];
    const float* qb = (const float*)d_in[4];
    const float* kw = (const float*)d_in[5];
    const float* kb = (const float*)d_in[6];
    const float* vw = (const float*)d_in[7];
    const float* vb = (const float*)d_in[8];
    const float* ow = (const float*)d_in[9];
    const float* ob = (const float*)d_in[10];
    const float* rt = (const float*)d_in[11];
    float* out = (float*)d_out;

    const int DSMEM_G = 3 * 32768;
    cudaFuncSetAttribute(gemm_mma_kernel,
                         cudaFuncAttributeMaxDynamicSharedMemorySize, DSMEM_G);
    const int DSMEM_A = 32768 + 2*32768 + 4096;    // 102400
    cudaFuncSetAttribute(attn_mma_kernel,
                         cudaFuncAttributeMaxDynamicSharedMemorySize, DSMEM_A);

    split_all_kernel<<<384 + 4*72, 256>>>(X, qw, kw, vw, ow);

    dim3 g1(EE/128, MT/128, 3);
    gemm_mma_kernel<<<g1, 256, DSMEM_G>>>(qb, kb, vb, nullptr, 0, 1);

    dim3 g2(SS/128, HH, BB);
    attn_mma_kernel<<<g2, 256, DSMEM_A>>>(pr, pc, rt);

    dim3 g3(EE/128, MT/128, 1);
    gemm_mma_kernel<<<g3, 256, DSMEM_G>>>(ob, ob, ob, out, 3, 0);
}

// round 11
// speedup vs baseline: 1.2461x; 1.2461x over previous
#include <cuda_runtime.h>
#include <cuda_bf16.h>
#include <cuda_fp16.h>
#include <cstdint>
#include <math.h>

#define BB 4
#define SS 1024
#define EE 768
#define HH 12
#define DD 64
#define MT (BB*SS)
#define SCALING 0.125f

// ---------------- device scratch (allocation-free rule) ----------------
__device__ __nv_bfloat16 g_Qhi[BB*HH*SS*DD], g_Qlo[BB*HH*SS*DD];
__device__ __nv_bfloat16 g_Khi[BB*HH*SS*DD], g_Klo[BB*HH*SS*DD];
__device__ __nv_bfloat16 g_Vhi[BB*HH*SS*DD], g_Vlo[BB*HH*SS*DD];
__device__ __half g_Xhi[MT*EE],  g_Xlo[MT*EE];
__device__ __half g_Wh[4*EE*EE];                  // weights: single fp16
__device__ __half g_AOhi[MT*EE], g_AOlo[MT*EE];

__device__ __forceinline__ uint32_t smem_u32(const void* p) {
    uint32_t a;
    asm("{ .reg .u64 t; cvta.to.shared.u64 t, %1; cvt.u32.u64 %0, t; }"
        : "=r"(a) : "l"(p));
    return a;
}

#define LDSM4(r, addr) \
    asm volatile("ldmatrix.sync.aligned.m8n8.x4.shared.b16 {%0,%1,%2,%3}, [%4];" \
        : "=r"((r)[0]), "=r"((r)[1]), "=r"((r)[2]), "=r"((r)[3]) : "r"(addr))
#define LDSM4T(r, addr) \
    asm volatile("ldmatrix.sync.aligned.m8n8.x4.trans.shared.b16 {%0,%1,%2,%3}, [%4];" \
        : "=r"((r)[0]), "=r"((r)[1]), "=r"((r)[2]), "=r"((r)[3]) : "r"(addr))

#define MMA_BF16(d, a, b0v, b1v) \
    asm volatile("mma.sync.aligned.m16n8k16.row.col.f32.bf16.bf16.f32 " \
        "{%0,%1,%2,%3}, {%4,%5,%6,%7}, {%8,%9}, {%0,%1,%2,%3};" \
        : "+f"((d)[0]), "+f"((d)[1]), "+f"((d)[2]), "+f"((d)[3]) \
        : "r"((a)[0]), "r"((a)[1]), "r"((a)[2]), "r"((a)[3]), "r"(b0v), "r"(b1v))

#define MMA_FP16(d, a, b0v, b1v) \
    asm volatile("mma.sync.aligned.m16n8k16.row.col.f32.f16.f16.f32 " \
        "{%0,%1,%2,%3}, {%4,%5,%6,%7}, {%8,%9}, {%0,%1,%2,%3};" \
        : "+f"((d)[0]), "+f"((d)[1]), "+f"((d)[2]), "+f"((d)[3]) \
        : "r"((a)[0]), "r"((a)[1]), "r"((a)[2]), "r"((a)[3]), "r"(b0v), "r"(b1v))

#define CP_ASYNC16(smem, gmem) \
    asm volatile("cp.async.cg.shared.global [%0], [%1], 16;" :: "r"(smem), "l"(gmem))
#define CP_COMMIT()  asm volatile("cp.async.commit_group;" ::: "memory")
#define CP_WAIT0()   asm volatile("cp.async.wait_group 0;" ::: "memory")
#define CP_WAIT1()   asm volatile("cp.async.wait_group 1;" ::: "memory")

// pack 2 fp32 -> bf16x2 hi + bf16x2 lo (3-split residual)
__device__ __forceinline__ void splitpack(float x, float y, uint32_t& hi, uint32_t& lo) {
    asm("cvt.rn.bf16x2.f32 %0, %1, %2;" : "=r"(hi) : "f"(y), "f"(x));
    float hx = __uint_as_float(hi << 16);
    float hy = __uint_as_float(hi & 0xffff0000u);
    float lx = x - hx, ly = y - hy;
    asm("cvt.rn.bf16x2.f32 %0, %1, %2;" : "=r"(lo) : "f"(ly), "f"(lx));
}

// pack 2 fp32 -> fp16x2 hi + fp16x2 lo
__device__ __forceinline__ void splitpack_h(float x, float y, uint32_t& hi, uint32_t& lo) {
    __half hx = __float2half_rn(x), hy = __float2half_rn(y);
    __half2 H = __halves2half2(hx, hy);
    hi = *(uint32_t*)&H;
    __half2 L = __floats2half2_rn(x - __half2float(hx), y - __half2float(hy));
    lo = *(uint32_t*)&L;
}

// ---------------------------------------------------------------------------
// split/convert: blocks [0,384) = X -> fp16 hi/lo; then 4x72 = W -> fp16
// ---------------------------------------------------------------------------
__global__ void __launch_bounds__(256) split_all_kernel(
    const float* __restrict__ X,
    const float* __restrict__ qw, const float* __restrict__ kw,
    const float* __restrict__ vw, const float* __restrict__ ow)
{
    const int bid = blockIdx.x;
    if (bid < 384) {
        size_t off = (size_t)bid * 8192;
        float4 v[8];
        #pragma unroll
        for (int u = 0; u < 8; u++)
            v[u] = *(const float4*)(X + off + u*1024 + threadIdx.x*4);
        #pragma unroll
        for (int u = 0; u < 8; u++) {
            size_t i = off + u*1024 + threadIdx.x*4;
            float xs[4] = {v[u].x, v[u].y, v[u].z, v[u].w};
            #pragma unroll
            for (int j = 0; j < 4; j++) {
                __half hv = __float2half_rn(xs[j]);
                g_Xhi[i+j] = hv;
                g_Xlo[i+j] = __float2half_rn(xs[j] - __half2float(hv));
            }
        }
    } else {
        int r = bid - 384;
        int slot = r / 72, rb = r % 72;
        const float* src = (slot == 0) ? qw : (slot == 1) ? kw : (slot == 2) ? vw : ow;
        __half* dst = g_Wh + (size_t)slot * EE * EE;
        size_t off = (size_t)rb * 8192;
        float4 v[8];
        #pragma unroll
        for (int u = 0; u < 8; u++)
            v[u] = *(const float4*)(src + off + u*1024 + threadIdx.x*4);
        #pragma unroll
        for (int u = 0; u < 8; u++) {
            size_t i = off + u*1024 + threadIdx.x*4;
            float xs[4] = {v[u].x, v[u].y, v[u].z, v[u].w};
            #pragma unroll
            for (int j = 0; j < 4; j++)
                dst[i+j] = __float2half_rn(xs[j]);
        }
    }
}

// ---------------------------------------------------------------------------
// HMMA GEMM (fp16, 2-term): D = (Ahi+Alo)(M,K) @ W(N,K)^T, fp32 accum.
// CTA 128x128, 8 warps (2x4), warp tile 64x32, BK=32, 3-stage cp.async,
// one __syncthreads per stage, 2 CTAs/SM. Stage = Ahi,Alo,Bh (24KB).
// is_qkv=1: A=g_X{hi,lo}, out = bf16 hi/lo Q/K/V [B,H,S,D] (+bias, Q scaled)
// is_qkv=0: A=g_AO{hi,lo}, out = outp fp32 [M,E] (+bias)
// ---------------------------------------------------------------------------
#define NS (EE/32)      // 24 K-stages
#define STAGE_B 24576u  // 3 x 8KB tiles
__global__ void __launch_bounds__(256, 2) gemm_mma_kernel(
    const float* __restrict__ b0p, const float* __restrict__ b1p,
    const float* __restrict__ b2p, float* __restrict__ outp,
    int wslot0, int is_qkv)
{
    extern __shared__ char dsm[];
    const uint32_t sbase = smem_u32(dsm);

    const int tid = threadIdx.x;
    const int wid = tid >> 5, lane = tid & 31;
    const int warp_m = wid & 1, warp_n = wid >> 1;
    const int m0w = warp_m * 64, n0w = warp_n * 32;

    const int z = is_qkv ? blockIdx.z : 0;
    const size_t woff = (size_t)(wslot0 + z) * EE * EE;
    const float* bias = (z == 0) ? b0p : (z == 1) ? b1p : b2p;
    const float scale = (is_qkv && z == 0) ? SCALING : 1.0f;
    __nv_bfloat16* outHi = (z == 0) ? g_Qhi : (z == 1) ? g_Khi : g_Vhi;
    __nv_bfloat16* outLo = (z == 0) ? g_Qlo : (z == 1) ? g_Klo : g_Vlo;

    const int n0 = blockIdx.x * 128;
    const int m0 = blockIdx.y * 128;

    const __half* s0 = (is_qkv ? g_Xhi : g_AOhi) + (size_t)m0 * EE;
    const __half* s1 = (is_qkv ? g_Xlo : g_AOlo) + (size_t)m0 * EE;
    const __half* s2 = g_Wh + woff + (size_t)n0 * EE;

    const int lrow = tid >> 2;
    const int lch  = tid & 3;
    auto stage_load = [&](int k0, int stg) {
        uint32_t sb = sbase + (uint32_t)stg * STAGE_B;
        #pragma unroll
        for (int t = 0; t < 3; t++) {
            const __half* sp = (t==0?s0:t==1?s1:s2) + k0 + lch*8;
            uint32_t tb = sb + (uint32_t)t * 8192u;
            #pragma unroll
            for (int j = 0; j < 2; j++) {
                int row = lrow + j*64;
                CP_ASYNC16(tb + row*64 + ((lch ^ ((row >> 1) & 3)) << 4),
                           sp + (size_t)row * EE);
            }
        }
        CP_COMMIT();
    };

    const int arow_sw = (lane >> 1) & 3;
    const int brow7 = (lane & 7) + ((lane >> 4) << 3);
    const int brow_sw = (brow7 >> 1) & 3;
    uint32_t aoff[4], boff[2];
    #pragma unroll
    for (int t = 0; t < 4; t++)
        aoff[t] = (uint32_t)(m0w + t*16 + (lane & 15)) * 64u;
    #pragma unroll
    for (int p = 0; p < 2; p++)
        boff[p] = (uint32_t)(n0w + p*16 + brow7) * 64u;
    const int achk = lane >> 4;
    const int bchk = (lane >> 3) & 1;

    float acc[4][4][4] = {};

    stage_load(0, 0);
    stage_load(32, 1);

    #pragma unroll 1
    for (int s = 0; s < NS; s++) {
        if (s == NS - 1) { CP_WAIT0(); } else { CP_WAIT1(); }
        __syncthreads();
        if (s + 2 < NS) stage_load((s + 2) * 32, (s + 2) % 3);

        const uint32_t stg = sbase + (uint32_t)(s % 3) * STAGE_B;
        const uint32_t Ahi = stg, Alo = stg + 8192u;
        const uint32_t Bh  = stg + 16384u;

        #pragma unroll
        for (int ks = 0; ks < 2; ks++) {
            const uint32_t asw = (uint32_t)((2*ks + achk) ^ arow_sw) << 4;
            const uint32_t bsw = (uint32_t)((2*ks + bchk) ^ brow_sw) << 4;
            uint32_t B[2][4];
            #pragma unroll
            for (int p = 0; p < 2; p++)
                LDSM4(B[p], Bh + boff[p] + bsw);
            #pragma unroll
            for (int t = 0; t < 4; t++) {
                uint32_t Ah[4], Al[4];
                LDSM4(Ah, Ahi + aoff[t] + asw);
                LDSM4(Al, Alo + aoff[t] + asw);
                #pragma unroll
                for (int n = 0; n < 4; n++) {
                    const int p = n >> 1, q = (n & 1) * 2;
                    MMA_FP16(acc[t][n], Ah, B[p][q], B[p][q+1]);
                }
                #pragma unroll
                for (int n = 0; n < 4; n++) {
                    const int p = n >> 1, q = (n & 1) * 2;
                    MMA_FP16(acc[t][n], Al, B[p][q], B[p][q+1]);
                }
            }
        }
    }

    // epilogue
    const int rl = lane >> 2, cl2 = (lane & 3) * 2;
    #pragma unroll
    for (int t = 0; t < 4; t++)
        #pragma unroll
        for (int n = 0; n < 4; n++) {
            const int col = n0 + n0w + n*8 + cl2;
            #pragma unroll
            for (int half = 0; half < 2; half++) {
                const int row = m0 + m0w + t*16 + rl + half*8;
                float ox = (acc[t][n][half*2+0] + bias[col+0]) * scale;
                float oy = (acc[t][n][half*2+1] + bias[col+1]) * scale;
                if (is_qkv) {
                    const int hh = col >> 6, d0 = col & 63;
                    const int bb_ = row >> 10, ss_ = row & 1023;
                    size_t idx = ((size_t)((bb_*HH + hh)*SS + ss_))*DD + d0;
                    uint32_t hi, lo;
                    splitpack(ox, oy, hi, lo);
                    *(uint32_t*)(outHi + idx) = hi;
                    *(uint32_t*)(outLo + idx) = lo;
                } else {
                    float2 o; o.x = ox; o.y = oy;
                    *(float2*)(outp + (size_t)row * EE + col) = o;
                }
            }
        }
}

// ---------------------------------------------------------------------------
// Flash attention on mma.sync bf16 (3-split) — UNCHANGED core (proven 346us
// config); epilogue now emits AO as fp16 hi/lo for the 2-term oproj.
// ---------------------------------------------------------------------------
__global__ void __launch_bounds__(256, 2) attn_mma_kernel(
    const int* __restrict__ pos_row, const int* __restrict__ pos_col,
    const float* __restrict__ rel_table)
{
    extern __shared__ char dsm[];
    const uint32_t sbase = smem_u32(dsm);
    const uint32_t sQhi = sbase, sQlo = sbase + 16384u;
    int* pk = (int*)(dsm + 98304);

    const int tid = threadIdx.x;
    const int wid = tid >> 5, lane = tid & 31;
    const int l7 = lane & 7;
    const int rl = lane >> 2, cl2 = (lane & 3) * 2;
    const int achk = lane >> 4;
    const int bchk = (lane >> 3) & 1;

    const int q0 = blockIdx.x * 128;
    const int h = blockIdx.y, b = blockIdx.z;
    const size_t hb = (size_t)(b*HH + h) * SS * DD;

    #pragma unroll
    for (int i = 0; i < 4; i++) {
        int s = tid + i*256;
        pk[s] = (pos_row[b*SS + s] << 5) | pos_col[b*SS + s];
    }

    {
        const int half = tid >> 7, r = tid & 127;
        const __nv_bfloat16* src = (half ? g_Qlo : g_Qhi) + hb + (size_t)(q0 + r)*DD;
        uint32_t dstrow = (half ? sQlo : sQhi) + (uint32_t)r * 128u;
        #pragma unroll
        for (int ch = 0; ch < 8; ch++)
            CP_ASYNC16(dstrow + ((ch ^ (r & 7)) << 4), src + ch*8);
        CP_COMMIT();
    }

    auto kv_load = [&](int kb, int stg) {
        const int t = tid >> 6, r = tid & 63;
        const __nv_bfloat16* src =
            (t==0 ? g_Khi : t==1 ? g_Klo : t==2 ? g_Vhi : g_Vlo)
            + hb + (size_t)(kb + r)*DD;
        uint32_t dstrow = sbase + 32768u + (uint32_t)stg*32768u
                        + (uint32_t)t*8192u + (uint32_t)r*128u;
        #pragma unroll
        for (int ch = 0; ch < 8; ch++)
            CP_ASYNC16(dstrow + ((ch ^ (r & 7)) << 4), src + ch*8);
        CP_COMMIT();
    };
    kv_load(0, 0);

    CP_WAIT1();
    __syncthreads();

    uint32_t qh[4][4], ql[4][4];
    const uint32_t aq = (uint32_t)(wid*16 + (lane & 15)) * 128u;
    #pragma unroll
    for (int ks = 0; ks < 4; ks++) {
        uint32_t sw = (uint32_t)((2*ks + achk) ^ l7) << 4;
        LDSM4(qh[ks], sQhi + aq + sw);
        LDSM4(ql[ks], sQlo + aq + sw);
    }

    const int rq0 = pk[q0 + wid*16 + rl];
    const int rq1 = pk[q0 + wid*16 + rl + 8];
    const float tb0 = rel_table[0*HH + h];
    const float tb1 = rel_table[1*HH + h];
    const float tb2 = rel_table[2*HH + h];
    const float tb3 = rel_table[3*HH + h];

    float oacc[8][4] = {};
    float m0 = -1e30f, m1 = -1e30f, l0 = 0.f, l1 = 0.f;

    #pragma unroll 1
    for (int kt = 0; kt < SS/64; kt++) {
        CP_WAIT0();
        __syncthreads();
        if (kt + 1 < SS/64) kv_load((kt + 1) * 64, (kt + 1) & 1);

        const uint32_t st  = sbase + 32768u + (uint32_t)(kt & 1) * 32768u;
        const uint32_t Khi = st, Klo = st + 8192u;
        const uint32_t Vhi = st + 16384u, Vlo = st + 24576u;

        float sacc[8][4] = {};
        #pragma unroll
        for (int ks = 0; ks < 4; ks++) {
            const uint32_t bsw = (uint32_t)((2*ks + bchk) ^ l7) << 4;
            #pragma unroll
            for (int p = 0; p < 4; p++) {
                const uint32_t bo =
                    (uint32_t)(p*16 + l7 + ((lane >> 4) << 3)) * 128u + bsw;
                uint32_t Bh[4], Bl[4];
                LDSM4(Bh, Khi + bo);
                LDSM4(Bl, Klo + bo);
                MMA_BF16(sacc[2*p],   qh[ks], Bh[0], Bh[1]);
                MMA_BF16(sacc[2*p+1], qh[ks], Bh[2], Bh[3]);
                MMA_BF16(sacc[2*p],   qh[ks], Bl[0], Bl[1]);
                MMA_BF16(sacc[2*p+1], qh[ks], Bl[2], Bl[3]);
                MMA_BF16(sacc[2*p],   ql[ks], Bh[0], Bh[1]);
                MMA_BF16(sacc[2*p+1], ql[ks], Bh[2], Bh[3]);
            }
        }

        const int kb = kt * 64;
        #pragma unroll
        for (int t = 0; t < 8; t++) {
            int c0 = kb + t*8 + cl2;
            int rk0 = pk[c0], rk1 = pk[c0 + 1];
            int x;
            x = rq0 ^ rk0; sacc[t][0] += (x < 32) ? (((x & 31) == 0) ? tb3 : tb1)
                                                  : (((x & 31) == 0) ? tb2 : tb0);
            x = rq0 ^ rk1; sacc[t][1] += (x < 32) ? (((x & 31) == 0) ? tb3 : tb1)
                                                  : (((x & 31) == 0) ? tb2 : tb0);
            x = rq1 ^ rk0; sacc[t][2] += (x < 32) ? (((x & 31) == 0) ? tb3 : tb1)
                                                  : (((x & 31) == 0) ? tb2 : tb0);
            x = rq1 ^ rk1; sacc[t][3] += (x < 32) ? (((x & 31) == 0) ? tb3 : tb1)
                                                  : (((x & 31) == 0) ? tb2 : tb0);
        }

        float mx0 = sacc[0][0], mx1 = sacc[0][2];
        #pragma unroll
        for (int t = 0; t < 8; t++) {
            mx0 = fmaxf(mx0, fmaxf(sacc[t][0], sacc[t][1]));
            mx1 = fmaxf(mx1, fmaxf(sacc[t][2], sacc[t][3]));
        }
        mx0 = fmaxf(mx0, __shfl_xor_sync(0xffffffffu, mx0, 1));
        mx0 = fmaxf(mx0, __shfl_xor_sync(0xffffffffu, mx0, 2));
        mx1 = fmaxf(mx1, __shfl_xor_sync(0xffffffffu, mx1, 1));
        mx1 = fmaxf(mx1, __shfl_xor_sync(0xffffffffu, mx1, 2));
        float mn0 = fmaxf(m0, mx0), mn1 = fmaxf(m1, mx1);
        float sc0 = __expf(m0 - mn0), sc1 = __expf(m1 - mn1);
        m0 = mn0; m1 = mn1;
        float rs0 = 0.f, rs1 = 0.f;
        #pragma unroll
        for (int t = 0; t < 8; t++) {
            sacc[t][0] = __expf(sacc[t][0] - mn0);
            sacc[t][1] = __expf(sacc[t][1] - mn0);
            sacc[t][2] = __expf(sacc[t][2] - mn1);
            sacc[t][3] = __expf(sacc[t][3] - mn1);
            rs0 += sacc[t][0] + sacc[t][1];
            rs1 += sacc[t][2] + sacc[t][3];
        }
        rs0 += __shfl_xor_sync(0xffffffffu, rs0, 1);
        rs0 += __shfl_xor_sync(0xffffffffu, rs0, 2);
        rs1 += __shfl_xor_sync(0xffffffffu, rs1, 1);
        rs1 += __shfl_xor_sync(0xffffffffu, rs1, 2);
        l0 = l0 * sc0 + rs0;
        l1 = l1 * sc1 + rs1;
        #pragma unroll
        for (int t = 0; t < 8; t++) {
            oacc[t][0] *= sc0; oacc[t][1] *= sc0;
            oacc[t][2] *= sc1; oacc[t][3] *= sc1;
        }

        #pragma unroll
        for (int ks = 0; ks < 4; ks++) {
            uint32_t ph[4], pl[4];
            splitpack(sacc[2*ks][0],   sacc[2*ks][1],   ph[0], pl[0]);
            splitpack(sacc[2*ks][2],   sacc[2*ks][3],   ph[1], pl[1]);
            splitpack(sacc[2*ks+1][0], sacc[2*ks+1][1], ph[2], pl[2]);
            splitpack(sacc[2*ks+1][2], sacc[2*ks+1][3], ph[3], pl[3]);
            const uint32_t vr =
                (uint32_t)(ks*16 + l7 + (((lane >> 3) & 1) << 3)) * 128u;
            #pragma unroll
            for (int p = 0; p < 4; p++) {
                const uint32_t vsw = (uint32_t)((2*p + achk) ^ l7) << 4;
                uint32_t Vh[4], Vl[4];
                LDSM4T(Vh, Vhi + vr + vsw);
                LDSM4T(Vl, Vlo + vr + vsw);
                MMA_BF16(oacc[2*p],   ph, Vh[0], Vh[1]);
                MMA_BF16(oacc[2*p+1], ph, Vh[2], Vh[3]);
                MMA_BF16(oacc[2*p],   ph, Vl[0], Vl[1]);
                MMA_BF16(oacc[2*p+1], ph, Vl[2], Vl[3]);
                MMA_BF16(oacc[2*p],   pl, Vh[0], Vh[1]);
                MMA_BF16(oacc[2*p+1], pl, Vh[2], Vh[3]);
            }
        }
    }

    // epilogue: normalize, emit fp16 hi/lo AO at [B,S,E] (e = h*64+d)
    const float inv0 = 1.0f / l0, inv1 = 1.0f / l1;
    const int qrow0 = q0 + wid*16 + rl;
    #pragma unroll
    for (int t = 0; t < 8; t++) {
        const int e = h*64 + t*8 + cl2;
        size_t i0 = (size_t)(b*SS + qrow0) * EE + e;
        size_t i1 = (size_t)(b*SS + qrow0 + 8) * EE + e;
        uint32_t hi, lo;
        splitpack_h(oacc[t][0] * inv0, oacc[t][1] * inv0, hi, lo);
        *(uint32_t*)(g_AOhi + i0) = hi;
        *(uint32_t*)(g_AOlo + i0) = lo;
        splitpack_h(oacc[t][2] * inv1, oacc[t][3] * inv1, hi, lo);
        *(uint32_t*)(g_AOhi + i1) = hi;
        *(uint32_t*)(g_AOlo + i1) = lo;
    }
}

// ---------------------------------------------------------------------------
extern "C" void kernel_launch(void* const* d_in, const int* in_sizes, int n_in,
                              void* d_out, int out_size) {
    const float* X  = (const float*)d_in[0];
    const int*   pr = (const int*)  d_in[1];
    const int*   pc = (const int*)  d_in[2];
    const float* qw = (const float*)d_in[3];
    const float* qb = (const float*)d_in[4];
    const float* kw = (const float*)d_in[5];
    const float* kb = (const float*)d_in[6];
    const float* vw = (const float*)d_in[7];
    const float* vb = (const float*)d_in[8];
    const float* ow = (const float*)d_in[9];
    const float* ob = (const float*)d_in[10];
    const float* rt = (const float*)d_in[11];
    float* out = (float*)d_out;

    const int DSMEM_G = 3 * 24576;                 // 3-stage, 24KB/stage
    cudaFuncSetAttribute(gemm_mma_kernel,
                         cudaFuncAttributeMaxDynamicSharedMemorySize, DSMEM_G);
    const int DSMEM_A = 32768 + 2*32768 + 4096;    // 102400
    cudaFuncSetAttribute(attn_mma_kernel,
                         cudaFuncAttributeMaxDynamicSharedMemorySize, DSMEM_A);

    split_all_kernel<<<384 + 4*72, 256>>>(X, qw, kw, vw, ow);

    dim3 g1(EE/128, MT/128, 3);
    gemm_mma_kernel<<<g1, 256, DSMEM_G>>>(qb, kb, vb, nullptr, 0, 1);

    dim3 g2(SS/128, HH, BB);
    attn_mma_kernel<<<g2, 256, DSMEM_A>>>(pr, pc, rt);

    dim3 g3(EE/128, MT/128, 1);
    gemm_mma_kernel<<<g3, 256, DSMEM_G>>>(ob, ob, ob, out, 3, 0);
}

// round 12
// speedup vs baseline: 1.4853x; 1.1920x over previous
#include <cuda_runtime.h>
#include <cuda_bf16.h>
#include <cuda_fp16.h>
#include <cstdint>
#include <math.h>

#define BB 4
#define SS 1024
#define EE 768
#define HH 12
#define DD 64
#define MT (BB*SS)
#define SCALING 0.125f

// ---------------- device scratch (allocation-free rule) ----------------
__device__ __half g_Qhi[BB*HH*SS*DD], g_Qlo[BB*HH*SS*DD];
__device__ __half g_Kh[BB*HH*SS*DD];      // K: single fp16
__device__ __half g_Vh[BB*HH*SS*DD];      // V: single fp16
__device__ __half g_Xhi[MT*EE],  g_Xlo[MT*EE];
__device__ __half g_Wh[4*EE*EE];          // weights: single fp16
__device__ __half g_AOhi[MT*EE], g_AOlo[MT*EE];

__device__ __forceinline__ uint32_t smem_u32(const void* p) {
    uint32_t a;
    asm("{ .reg .u64 t; cvta.to.shared.u64 t, %1; cvt.u32.u64 %0, t; }"
        : "=r"(a) : "l"(p));
    return a;
}

#define LDSM4(r, addr) \
    asm volatile("ldmatrix.sync.aligned.m8n8.x4.shared.b16 {%0,%1,%2,%3}, [%4];" \
        : "=r"((r)[0]), "=r"((r)[1]), "=r"((r)[2]), "=r"((r)[3]) : "r"(addr))
#define LDSM4T(r, addr) \
    asm volatile("ldmatrix.sync.aligned.m8n8.x4.trans.shared.b16 {%0,%1,%2,%3}, [%4];" \
        : "=r"((r)[0]), "=r"((r)[1]), "=r"((r)[2]), "=r"((r)[3]) : "r"(addr))

#define MMA_FP16(d, a, b0v, b1v) \
    asm volatile("mma.sync.aligned.m16n8k16.row.col.f32.f16.f16.f32 " \
        "{%0,%1,%2,%3}, {%4,%5,%6,%7}, {%8,%9}, {%0,%1,%2,%3};" \
        : "+f"((d)[0]), "+f"((d)[1]), "+f"((d)[2]), "+f"((d)[3]) \
        : "r"((a)[0]), "r"((a)[1]), "r"((a)[2]), "r"((a)[3]), "r"(b0v), "r"(b1v))

#define CP_ASYNC16(smem, gmem) \
    asm volatile("cp.async.cg.shared.global [%0], [%1], 16;" :: "r"(smem), "l"(gmem))
#define CP_COMMIT()  asm volatile("cp.async.commit_group;" ::: "memory")
#define CP_WAIT0()   asm volatile("cp.async.wait_group 0;" ::: "memory")
#define CP_WAIT1()   asm volatile("cp.async.wait_group 1;" ::: "memory")

// pack 2 fp32 -> fp16x2 hi + fp16x2 lo
__device__ __forceinline__ void splitpack_h(float x, float y, uint32_t& hi, uint32_t& lo) {
    __half hx = __float2half_rn(x), hy = __float2half_rn(y);
    __half2 H = __halves2half2(hx, hy);
    hi = *(uint32_t*)&H;
    __half2 L = __floats2half2_rn(x - __half2float(hx), y - __half2float(hy));
    lo = *(uint32_t*)&L;
}

// ---------------------------------------------------------------------------
// split/convert: blocks [0,384) = X -> fp16 hi/lo; then 4x72 = W -> fp16
// ---------------------------------------------------------------------------
__global__ void __launch_bounds__(256) split_all_kernel(
    const float* __restrict__ X,
    const float* __restrict__ qw, const float* __restrict__ kw,
    const float* __restrict__ vw, const float* __restrict__ ow)
{
    const int bid = blockIdx.x;
    if (bid < 384) {
        size_t off = (size_t)bid * 8192;
        float4 v[8];
        #pragma unroll
        for (int u = 0; u < 8; u++)
            v[u] = *(const float4*)(X + off + u*1024 + threadIdx.x*4);
        #pragma unroll
        for (int u = 0; u < 8; u++) {
            size_t i = off + u*1024 + threadIdx.x*4;
            float xs[4] = {v[u].x, v[u].y, v[u].z, v[u].w};
            #pragma unroll
            for (int j = 0; j < 4; j++) {
                __half hv = __float2half_rn(xs[j]);
                g_Xhi[i+j] = hv;
                g_Xlo[i+j] = __float2half_rn(xs[j] - __half2float(hv));
            }
        }
    } else {
        int r = bid - 384;
        int slot = r / 72, rb = r % 72;
        const float* src = (slot == 0) ? qw : (slot == 1) ? kw : (slot == 2) ? vw : ow;
        __half* dst = g_Wh + (size_t)slot * EE * EE;
        size_t off = (size_t)rb * 8192;
        float4 v[8];
        #pragma unroll
        for (int u = 0; u < 8; u++)
            v[u] = *(const float4*)(src + off + u*1024 + threadIdx.x*4);
        #pragma unroll
        for (int u = 0; u < 8; u++) {
            size_t i = off + u*1024 + threadIdx.x*4;
            float xs[4] = {v[u].x, v[u].y, v[u].z, v[u].w};
            #pragma unroll
            for (int j = 0; j < 4; j++)
                dst[i+j] = __float2half_rn(xs[j]);
        }
    }
}

// ---------------------------------------------------------------------------
// HMMA GEMM (fp16, 2-term): D = (Ahi+Alo)(M,K) @ W(N,K)^T, fp32 accum.
// CTA 128x128, 8 warps (2x4), warp tile 64x32, BK=32, 3-stage cp.async.
// is_qkv=1: out = Q as fp16 hi/lo, K/V as single fp16, [B,H,S,D] layout.
// is_qkv=0: out = outp fp32 [M,E] (+bias)
// ---------------------------------------------------------------------------
#define NS (EE/32)      // 24 K-stages
#define STAGE_B 24576u  // 3 x 8KB tiles
__global__ void __launch_bounds__(256, 2) gemm_mma_kernel(
    const float* __restrict__ b0p, const float* __restrict__ b1p,
    const float* __restrict__ b2p, float* __restrict__ outp,
    int wslot0, int is_qkv)
{
    extern __shared__ char dsm[];
    const uint32_t sbase = smem_u32(dsm);

    const int tid = threadIdx.x;
    const int wid = tid >> 5, lane = tid & 31;
    const int warp_m = wid & 1, warp_n = wid >> 1;
    const int m0w = warp_m * 64, n0w = warp_n * 32;

    const int z = is_qkv ? blockIdx.z : 0;
    const size_t woff = (size_t)(wslot0 + z) * EE * EE;
    const float* bias = (z == 0) ? b0p : (z == 1) ? b1p : b2p;
    const float scale = (is_qkv && z == 0) ? SCALING : 1.0f;

    const int n0 = blockIdx.x * 128;
    const int m0 = blockIdx.y * 128;

    const __half* s0 = (is_qkv ? g_Xhi : g_AOhi) + (size_t)m0 * EE;
    const __half* s1 = (is_qkv ? g_Xlo : g_AOlo) + (size_t)m0 * EE;
    const __half* s2 = g_Wh + woff + (size_t)n0 * EE;

    const int lrow = tid >> 2;
    const int lch  = tid & 3;
    auto stage_load = [&](int k0, int stg) {
        uint32_t sb = sbase + (uint32_t)stg * STAGE_B;
        #pragma unroll
        for (int t = 0; t < 3; t++) {
            const __half* sp = (t==0?s0:t==1?s1:s2) + k0 + lch*8;
            uint32_t tb = sb + (uint32_t)t * 8192u;
            #pragma unroll
            for (int j = 0; j < 2; j++) {
                int row = lrow + j*64;
                CP_ASYNC16(tb + row*64 + ((lch ^ ((row >> 1) & 3)) << 4),
                           sp + (size_t)row * EE);
            }
        }
        CP_COMMIT();
    };

    const int arow_sw = (lane >> 1) & 3;
    const int brow7 = (lane & 7) + ((lane >> 4) << 3);
    const int brow_sw = (brow7 >> 1) & 3;
    uint32_t aoff[4], boff[2];
    #pragma unroll
    for (int t = 0; t < 4; t++)
        aoff[t] = (uint32_t)(m0w + t*16 + (lane & 15)) * 64u;
    #pragma unroll
    for (int p = 0; p < 2; p++)
        boff[p] = (uint32_t)(n0w + p*16 + brow7) * 64u;
    const int achk = lane >> 4;
    const int bchk = (lane >> 3) & 1;

    float acc[4][4][4] = {};

    stage_load(0, 0);
    stage_load(32, 1);

    #pragma unroll 1
    for (int s = 0; s < NS; s++) {
        if (s == NS - 1) { CP_WAIT0(); } else { CP_WAIT1(); }
        __syncthreads();
        if (s + 2 < NS) stage_load((s + 2) * 32, (s + 2) % 3);

        const uint32_t stg = sbase + (uint32_t)(s % 3) * STAGE_B;
        const uint32_t Ahi = stg, Alo = stg + 8192u;
        const uint32_t Bh  = stg + 16384u;

        #pragma unroll
        for (int ks = 0; ks < 2; ks++) {
            const uint32_t asw = (uint32_t)((2*ks + achk) ^ arow_sw) << 4;
            const uint32_t bsw = (uint32_t)((2*ks + bchk) ^ brow_sw) << 4;
            uint32_t B[2][4];
            #pragma unroll
            for (int p = 0; p < 2; p++)
                LDSM4(B[p], Bh + boff[p] + bsw);
            #pragma unroll
            for (int t = 0; t < 4; t++) {
                uint32_t Ah[4], Al[4];
                LDSM4(Ah, Ahi + aoff[t] + asw);
                LDSM4(Al, Alo + aoff[t] + asw);
                #pragma unroll
                for (int n = 0; n < 4; n++) {
                    const int p = n >> 1, q = (n & 1) * 2;
                    MMA_FP16(acc[t][n], Ah, B[p][q], B[p][q+1]);
                }
                #pragma unroll
                for (int n = 0; n < 4; n++) {
                    const int p = n >> 1, q = (n & 1) * 2;
                    MMA_FP16(acc[t][n], Al, B[p][q], B[p][q+1]);
                }
            }
        }
    }

    // epilogue
    const int rl = lane >> 2, cl2 = (lane & 3) * 2;
    #pragma unroll
    for (int t = 0; t < 4; t++)
        #pragma unroll
        for (int n = 0; n < 4; n++) {
            const int col = n0 + n0w + n*8 + cl2;
            #pragma unroll
            for (int half = 0; half < 2; half++) {
                const int row = m0 + m0w + t*16 + rl + half*8;
                float ox = (acc[t][n][half*2+0] + bias[col+0]) * scale;
                float oy = (acc[t][n][half*2+1] + bias[col+1]) * scale;
                if (is_qkv) {
                    const int hh = col >> 6, d0 = col & 63;
                    const int bb_ = row >> 10, ss_ = row & 1023;
                    size_t idx = ((size_t)((bb_*HH + hh)*SS + ss_))*DD + d0;
                    if (z == 0) {
                        uint32_t hi, lo;
                        splitpack_h(ox, oy, hi, lo);
                        *(uint32_t*)(g_Qhi + idx) = hi;
                        *(uint32_t*)(g_Qlo + idx) = lo;
                    } else {
                        __half2 h2 = __floats2half2_rn(ox, oy);
                        *(__half2*)((z == 1 ? g_Kh : g_Vh) + idx) = h2;
                    }
                } else {
                    float2 o; o.x = ox; o.y = oy;
                    *(float2*)(outp + (size_t)row * EE + col) = o;
                }
            }
        }
}

// ---------------------------------------------------------------------------
// Flash attention, fp16 2-term everywhere: S = (Qhi+Qlo)·K, O = (Phi+Plo)·V,
// K and V single fp16 (safe: logits are small, error analysis in journal).
// CTA = 128 Q rows x (b,h). 8 warps, warp = m16 x n64. K/V chunks of 64 rows,
// double-buffered cp.async. Smem: Qhi/Qlo 32KB | 2 x 16KB KV | pk 4KB = 68KB.
// ---------------------------------------------------------------------------
__global__ void __launch_bounds__(256, 2) attn_mma_kernel(
    const int* __restrict__ pos_row, const int* __restrict__ pos_col,
    const float* __restrict__ rel_table)
{
    extern __shared__ char dsm[];
    const uint32_t sbase = smem_u32(dsm);
    const uint32_t sQhi = sbase, sQlo = sbase + 16384u;
    int* pk = (int*)(dsm + 65536);

    const int tid = threadIdx.x;
    const int wid = tid >> 5, lane = tid & 31;
    const int l7 = lane & 7;
    const int rl = lane >> 2, cl2 = (lane & 3) * 2;
    const int achk = lane >> 4;
    const int bchk = (lane >> 3) & 1;

    const int q0 = blockIdx.x * 128;
    const int h = blockIdx.y, b = blockIdx.z;
    const size_t hb = (size_t)(b*HH + h) * SS * DD;

    #pragma unroll
    for (int i = 0; i < 4; i++) {
        int s = tid + i*256;
        pk[s] = (pos_row[b*SS + s] << 5) | pos_col[b*SS + s];
    }

    // Q stage: 128 rows x 64 fp16 hi/lo
    {
        const int half = tid >> 7, r = tid & 127;
        const __half* src = (half ? g_Qlo : g_Qhi) + hb + (size_t)(q0 + r)*DD;
        uint32_t dstrow = (half ? sQlo : sQhi) + (uint32_t)r * 128u;
        #pragma unroll
        for (int ch = 0; ch < 8; ch++)
            CP_ASYNC16(dstrow + ((ch ^ (r & 7)) << 4), src + ch*8);
        CP_COMMIT();
    }

    // KV stage: K 8KB + V 8KB = 16KB per stage
    auto kv_load = [&](int kb, int stg) {
        const int t = tid >> 7;                // 0=K, 1=V
        const int r = tid & 63;                // row in tile
        const int hf = (tid >> 6) & 1;         // chunk half
        const __half* src = (t == 0 ? g_Kh : g_Vh) + hb + (size_t)(kb + r)*DD;
        uint32_t dstrow = sbase + 32768u + (uint32_t)stg*16384u
                        + (uint32_t)t*8192u + (uint32_t)r*128u;
        #pragma unroll
        for (int j = 0; j < 4; j++) {
            int ch = hf*4 + j;
            CP_ASYNC16(dstrow + ((ch ^ (r & 7)) << 4), src + ch*8);
        }
        CP_COMMIT();
    };
    kv_load(0, 0);

    CP_WAIT1();
    __syncthreads();

    uint32_t qh[4][4], ql[4][4];
    const uint32_t aq = (uint32_t)(wid*16 + (lane & 15)) * 128u;
    #pragma unroll
    for (int ks = 0; ks < 4; ks++) {
        uint32_t sw = (uint32_t)((2*ks + achk) ^ l7) << 4;
        LDSM4(qh[ks], sQhi + aq + sw);
        LDSM4(ql[ks], sQlo + aq + sw);
    }

    const int rq0 = pk[q0 + wid*16 + rl];
    const int rq1 = pk[q0 + wid*16 + rl + 8];
    const float tb0 = rel_table[0*HH + h];
    const float tb1 = rel_table[1*HH + h];
    const float tb2 = rel_table[2*HH + h];
    const float tb3 = rel_table[3*HH + h];

    float oacc[8][4] = {};
    float m0 = -1e30f, m1 = -1e30f, l0 = 0.f, l1 = 0.f;

    #pragma unroll 1
    for (int kt = 0; kt < SS/64; kt++) {
        CP_WAIT0();
        __syncthreads();
        if (kt + 1 < SS/64) kv_load((kt + 1) * 64, (kt + 1) & 1);

        const uint32_t st = sbase + 32768u + (uint32_t)(kt & 1) * 16384u;
        const uint32_t Kt = st, Vt = st + 8192u;

        // S = (Qhi+Qlo) K^T  (m16 x n64), fp32 accum, K single fp16
        float sacc[8][4] = {};
        #pragma unroll
        for (int ks = 0; ks < 4; ks++) {
            const uint32_t bsw = (uint32_t)((2*ks + bchk) ^ l7) << 4;
            #pragma unroll
            for (int p = 0; p < 4; p++) {
                const uint32_t bo =
                    (uint32_t)(p*16 + l7 + ((lane >> 4) << 3)) * 128u + bsw;
                uint32_t B[4];
                LDSM4(B, Kt + bo);
                MMA_FP16(sacc[2*p],   qh[ks], B[0], B[1]);
                MMA_FP16(sacc[2*p+1], qh[ks], B[2], B[3]);
                MMA_FP16(sacc[2*p],   ql[ks], B[0], B[1]);
                MMA_FP16(sacc[2*p+1], ql[ks], B[2], B[3]);
            }
        }

        // bias
        const int kb = kt * 64;
        #pragma unroll
        for (int t = 0; t < 8; t++) {
            int c0 = kb + t*8 + cl2;
            int rk0 = pk[c0], rk1 = pk[c0 + 1];
            int x;
            x = rq0 ^ rk0; sacc[t][0] += (x < 32) ? (((x & 31) == 0) ? tb3 : tb1)
                                                  : (((x & 31) == 0) ? tb2 : tb0);
            x = rq0 ^ rk1; sacc[t][1] += (x < 32) ? (((x & 31) == 0) ? tb3 : tb1)
                                                  : (((x & 31) == 0) ? tb2 : tb0);
            x = rq1 ^ rk0; sacc[t][2] += (x < 32) ? (((x & 31) == 0) ? tb3 : tb1)
                                                  : (((x & 31) == 0) ? tb2 : tb0);
            x = rq1 ^ rk1; sacc[t][3] += (x < 32) ? (((x & 31) == 0) ? tb3 : tb1)
                                                  : (((x & 31) == 0) ? tb2 : tb0);
        }

        // online softmax (MUFU exp; 4 lanes/row)
        float mx0 = sacc[0][0], mx1 = sacc[0][2];
        #pragma unroll
        for (int t = 0; t < 8; t++) {
            mx0 = fmaxf(mx0, fmaxf(sacc[t][0], sacc[t][1]));
            mx1 = fmaxf(mx1, fmaxf(sacc[t][2], sacc[t][3]));
        }
        mx0 = fmaxf(mx0, __shfl_xor_sync(0xffffffffu, mx0, 1));
        mx0 = fmaxf(mx0, __shfl_xor_sync(0xffffffffu, mx0, 2));
        mx1 = fmaxf(mx1, __shfl_xor_sync(0xffffffffu, mx1, 1));
        mx1 = fmaxf(mx1, __shfl_xor_sync(0xffffffffu, mx1, 2));
        float mn0 = fmaxf(m0, mx0), mn1 = fmaxf(m1, mx1);
        float sc0 = __expf(m0 - mn0), sc1 = __expf(m1 - mn1);
        m0 = mn0; m1 = mn1;
        float rs0 = 0.f, rs1 = 0.f;
        #pragma unroll
        for (int t = 0; t < 8; t++) {
            sacc[t][0] = __expf(sacc[t][0] - mn0);
            sacc[t][1] = __expf(sacc[t][1] - mn0);
            sacc[t][2] = __expf(sacc[t][2] - mn1);
            sacc[t][3] = __expf(sacc[t][3] - mn1);
            rs0 += sacc[t][0] + sacc[t][1];
            rs1 += sacc[t][2] + sacc[t][3];
        }
        rs0 += __shfl_xor_sync(0xffffffffu, rs0, 1);
        rs0 += __shfl_xor_sync(0xffffffffu, rs0, 2);
        rs1 += __shfl_xor_sync(0xffffffffu, rs1, 1);
        rs1 += __shfl_xor_sync(0xffffffffu, rs1, 2);
        l0 = l0 * sc0 + rs0;
        l1 = l1 * sc1 + rs1;
        #pragma unroll
        for (int t = 0; t < 8; t++) {
            oacc[t][0] *= sc0; oacc[t][1] *= sc0;
            oacc[t][2] *= sc1; oacc[t][3] *= sc1;
        }

        // O += (Phi+Plo) V : P fragments from sacc, V single fp16
        #pragma unroll
        for (int ks = 0; ks < 4; ks++) {
            uint32_t ph[4], pl[4];
            splitpack_h(sacc[2*ks][0],   sacc[2*ks][1],   ph[0], pl[0]);
            splitpack_h(sacc[2*ks][2],   sacc[2*ks][3],   ph[1], pl[1]);
            splitpack_h(sacc[2*ks+1][0], sacc[2*ks+1][1], ph[2], pl[2]);
            splitpack_h(sacc[2*ks+1][2], sacc[2*ks+1][3], ph[3], pl[3]);
            const uint32_t vr =
                (uint32_t)(ks*16 + l7 + (((lane >> 3) & 1) << 3)) * 128u;
            #pragma unroll
            for (int p = 0; p < 4; p++) {
                const uint32_t vsw = (uint32_t)((2*p + achk) ^ l7) << 4;
                uint32_t V[4];
                LDSM4T(V, Vt + vr + vsw);
                MMA_FP16(oacc[2*p],   ph, V[0], V[1]);
                MMA_FP16(oacc[2*p+1], ph, V[2], V[3]);
                MMA_FP16(oacc[2*p],   pl, V[0], V[1]);
                MMA_FP16(oacc[2*p+1], pl, V[2], V[3]);
            }
        }
    }

    // epilogue: normalize, emit fp16 hi/lo AO at [B,S,E] (e = h*64+d)
    const float inv0 = 1.0f / l0, inv1 = 1.0f / l1;
    const int qrow0 = q0 + wid*16 + rl;
    #pragma unroll
    for (int t = 0; t < 8; t++) {
        const int e = h*64 + t*8 + cl2;
        size_t i0 = (size_t)(b*SS + qrow0) * EE + e;
        size_t i1 = (size_t)(b*SS + qrow0 + 8) * EE + e;
        uint32_t hi, lo;
        splitpack_h(oacc[t][0] * inv0, oacc[t][1] * inv0, hi, lo);
        *(uint32_t*)(g_AOhi + i0) = hi;
        *(uint32_t*)(g_AOlo + i0) = lo;
        splitpack_h(oacc[t][2] * inv1, oacc[t][3] * inv1, hi, lo);
        *(uint32_t*)(g_AOhi + i1) = hi;
        *(uint32_t*)(g_AOlo + i1) = lo;
    }
}

// ---------------------------------------------------------------------------
extern "C" void kernel_launch(void* const* d_in, const int* in_sizes, int n_in,
                              void* d_out, int out_size) {
    const float* X  = (const float*)d_in[0];
    const int*   pr = (const int*)  d_in[1];
    const int*   pc = (const int*)  d_in[2];
    const float* qw = (const float*)d_in[3];
    const float* qb = (const float*)d_in[4];
    const float* kw = (const float*)d_in[5];
    const float* kb = (const float*)d_in[6];
    const float* vw = (const float*)d_in[7];
    const float* vb = (const float*)d_in[8];
    const float* ow = (const float*)d_in[9];
    const float* ob = (const float*)d_in[10];
    const float* rt = (const float*)d_in[11];
    float* out = (float*)d_out;

    const int DSMEM_G = 3 * 24576;                 // 3-stage, 24KB/stage
    cudaFuncSetAttribute(gemm_mma_kernel,
                         cudaFuncAttributeMaxDynamicSharedMemorySize, DSMEM_G);
    const int DSMEM_A = 32768 + 2*16384 + 4096;    // 69632
    cudaFuncSetAttribute(attn_mma_kernel,
                         cudaFuncAttributeMaxDynamicSharedMemorySize, DSMEM_A);

    split_all_kernel<<<384 + 4*72, 256>>>(X, qw, kw, vw, ow);

    dim3 g1(EE/128, MT/128, 3);
    gemm_mma_kernel<<<g1, 256, DSMEM_G>>>(qb, kb, vb, nullptr, 0, 1);

    dim3 g2(SS/128, HH, BB);
    attn_mma_kernel<<<g2, 256, DSMEM_A>>>(pr, pc, rt);

    dim3 g3(EE/128, MT/128, 1);
    gemm_mma_kernel<<<g3, 256, DSMEM_G>>>(ob, ob, ob, out, 3, 0);
}

// round 13
// speedup vs baseline: 1.8839x; 1.2683x over previous
#include <cuda_runtime.h>
#include <cuda_bf16.h>
#include <cuda_fp16.h>
#include <cstdint>
#include <math.h>

#define BB 4
#define SS 1024
#define EE 768
#define HH 12
#define DD 64
#define MT (BB*SS)
#define SCALING 0.125f

// ---------------- device scratch (allocation-free rule) ----------------
__device__ __half g_Qh[BB*HH*SS*DD];      // Q: single fp16 (scaled)
__device__ __half g_Kh[BB*HH*SS*DD];      // K: single fp16
__device__ __half g_Vh[BB*HH*SS*DD];      // V: single fp16
__device__ __half g_Xh[MT*EE];            // X: single fp16
__device__ __half g_Wh[4*EE*EE];          // weights: single fp16
__device__ __half g_AOhi[MT*EE], g_AOlo[MT*EE];   // AO keeps hi/lo (ballast)

__device__ __forceinline__ uint32_t smem_u32(const void* p) {
    uint32_t a;
    asm("{ .reg .u64 t; cvta.to.shared.u64 t, %1; cvt.u32.u64 %0, t; }"
        : "=r"(a) : "l"(p));
    return a;
}

#define LDSM4(r, addr) \
    asm volatile("ldmatrix.sync.aligned.m8n8.x4.shared.b16 {%0,%1,%2,%3}, [%4];" \
        : "=r"((r)[0]), "=r"((r)[1]), "=r"((r)[2]), "=r"((r)[3]) : "r"(addr))
#define LDSM4T(r, addr) \
    asm volatile("ldmatrix.sync.aligned.m8n8.x4.trans.shared.b16 {%0,%1,%2,%3}, [%4];" \
        : "=r"((r)[0]), "=r"((r)[1]), "=r"((r)[2]), "=r"((r)[3]) : "r"(addr))

#define MMA_FP16(d, a, b0v, b1v) \
    asm volatile("mma.sync.aligned.m16n8k16.row.col.f32.f16.f16.f32 " \
        "{%0,%1,%2,%3}, {%4,%5,%6,%7}, {%8,%9}, {%0,%1,%2,%3};" \
        : "+f"((d)[0]), "+f"((d)[1]), "+f"((d)[2]), "+f"((d)[3]) \
        : "r"((a)[0]), "r"((a)[1]), "r"((a)[2]), "r"((a)[3]), "r"(b0v), "r"(b1v))

#define CP_ASYNC16(smem, gmem) \
    asm volatile("cp.async.cg.shared.global [%0], [%1], 16;" :: "r"(smem), "l"(gmem))
#define CP_COMMIT()  asm volatile("cp.async.commit_group;" ::: "memory")
#define CP_WAIT0()   asm volatile("cp.async.wait_group 0;" ::: "memory")
#define CP_WAIT1()   asm volatile("cp.async.wait_group 1;" ::: "memory")

// pack 2 fp32 -> fp16x2 hi + fp16x2 lo
__device__ __forceinline__ void splitpack_h(float x, float y, uint32_t& hi, uint32_t& lo) {
    __half hx = __float2half_rn(x), hy = __float2half_rn(y);
    __half2 H = __halves2half2(hx, hy);
    hi = *(uint32_t*)&H;
    __half2 L = __floats2half2_rn(x - __half2float(hx), y - __half2float(hy));
    lo = *(uint32_t*)&L;
}

// ---------------------------------------------------------------------------
// convert: blocks [0,384) = X -> single fp16; then 4x72 = W -> single fp16
// ---------------------------------------------------------------------------
__global__ void __launch_bounds__(256) split_all_kernel(
    const float* __restrict__ X,
    const float* __restrict__ qw, const float* __restrict__ kw,
    const float* __restrict__ vw, const float* __restrict__ ow)
{
    const int bid = blockIdx.x;
    const float* src;
    __half* dst;
    size_t off;
    if (bid < 384) {
        src = X; dst = g_Xh; off = (size_t)bid * 8192;
    } else {
        int r = bid - 384;
        int slot = r / 72, rb = r % 72;
        src = (slot == 0) ? qw : (slot == 1) ? kw : (slot == 2) ? vw : ow;
        dst = g_Wh + (size_t)slot * EE * EE;
        off = (size_t)rb * 8192;
    }
    float4 v[8];
    #pragma unroll
    for (int u = 0; u < 8; u++)
        v[u] = *(const float4*)(src + off + u*1024 + threadIdx.x*4);
    #pragma unroll
    for (int u = 0; u < 8; u++) {
        size_t i = off + u*1024 + threadIdx.x*4;
        __half2 a = __floats2half2_rn(v[u].x, v[u].y);
        __half2 b = __floats2half2_rn(v[u].z, v[u].w);
        *(__half2*)(dst + i)     = a;
        *(__half2*)(dst + i + 2) = b;
    }
}

// ---------------------------------------------------------------------------
// HMMA GEMM templated on TERMS: D = (sum of A terms)(M,K) @ W(N,K)^T, fp32 acc.
// CTA 128x128, 8 warps (2x4), warp tile 64x32, BK=32, 3-stage cp.async.
// TERMS=1 (qkv): A = g_Xh;   out = Q/K/V single fp16, [B,H,S,D], Q scaled.
// TERMS=2 (oproj): A = g_AO{hi,lo}; out = outp fp32 [M,E] (+bias).
// ---------------------------------------------------------------------------
#define NS (EE/32)      // 24 K-stages
template<int TERMS>
__global__ void __launch_bounds__(256, 2) gemm_mma_kernel(
    const float* __restrict__ b0p, const float* __restrict__ b1p,
    const float* __restrict__ b2p, float* __restrict__ outp,
    int wslot0, int is_qkv)
{
    extern __shared__ char dsm[];
    const uint32_t sbase = smem_u32(dsm);
    constexpr uint32_t STG_B = (TERMS + 1) * 8192u;

    const int tid = threadIdx.x;
    const int wid = tid >> 5, lane = tid & 31;
    const int warp_m = wid & 1, warp_n = wid >> 1;
    const int m0w = warp_m * 64, n0w = warp_n * 32;

    const int z = is_qkv ? blockIdx.z : 0;
    const size_t woff = (size_t)(wslot0 + z) * EE * EE;
    const float* bias = (z == 0) ? b0p : (z == 1) ? b1p : b2p;
    const float scale = (is_qkv && z == 0) ? SCALING : 1.0f;
    __half* outH = (z == 0) ? g_Qh : (z == 1) ? g_Kh : g_Vh;

    const int n0 = blockIdx.x * 128;
    const int m0 = blockIdx.y * 128;

    const __half* s0 = (is_qkv ? g_Xh : g_AOhi) + (size_t)m0 * EE;
    const __half* s1 = g_AOlo + (size_t)m0 * EE;   // used only when TERMS==2
    const __half* s2 = g_Wh + woff + (size_t)n0 * EE;

    const int lrow = tid >> 2;
    const int lch  = tid & 3;
    auto stage_load = [&](int k0, int stg) {
        uint32_t sb = sbase + (uint32_t)stg * STG_B;
        #pragma unroll
        for (int t = 0; t <= TERMS; t++) {
            const __half* sp = (t == 0 ? s0 : (t == TERMS ? s2 : s1)) + k0 + lch*8;
            uint32_t tb = sb + (uint32_t)t * 8192u;
            #pragma unroll
            for (int j = 0; j < 2; j++) {
                int row = lrow + j*64;
                CP_ASYNC16(tb + row*64 + ((lch ^ ((row >> 1) & 3)) << 4),
                           sp + (size_t)row * EE);
            }
        }
        CP_COMMIT();
    };

    const int arow_sw = (lane >> 1) & 3;
    const int brow7 = (lane & 7) + ((lane >> 4) << 3);
    const int brow_sw = (brow7 >> 1) & 3;
    uint32_t aoff[4], boff[2];
    #pragma unroll
    for (int t = 0; t < 4; t++)
        aoff[t] = (uint32_t)(m0w + t*16 + (lane & 15)) * 64u;
    #pragma unroll
    for (int p = 0; p < 2; p++)
        boff[p] = (uint32_t)(n0w + p*16 + brow7) * 64u;
    const int achk = lane >> 4;
    const int bchk = (lane >> 3) & 1;

    float acc[4][4][4] = {};

    stage_load(0, 0);
    stage_load(32, 1);

    #pragma unroll 1
    for (int s = 0; s < NS; s++) {
        if (s == NS - 1) { CP_WAIT0(); } else { CP_WAIT1(); }
        __syncthreads();
        if (s + 2 < NS) stage_load((s + 2) * 32, (s + 2) % 3);

        const uint32_t stg = sbase + (uint32_t)(s % 3) * STG_B;
        const uint32_t Ahi = stg;
        const uint32_t Alo = stg + 8192u;                    // TERMS==2 only
        const uint32_t Bh  = stg + (uint32_t)TERMS * 8192u;

        #pragma unroll
        for (int ks = 0; ks < 2; ks++) {
            const uint32_t asw = (uint32_t)((2*ks + achk) ^ arow_sw) << 4;
            const uint32_t bsw = (uint32_t)((2*ks + bchk) ^ brow_sw) << 4;
            uint32_t B[2][4];
            #pragma unroll
            for (int p = 0; p < 2; p++)
                LDSM4(B[p], Bh + boff[p] + bsw);
            #pragma unroll
            for (int t = 0; t < 4; t++) {
                uint32_t Ah[4];
                LDSM4(Ah, Ahi + aoff[t] + asw);
                #pragma unroll
                for (int n = 0; n < 4; n++) {
                    const int p = n >> 1, q = (n & 1) * 2;
                    MMA_FP16(acc[t][n], Ah, B[p][q], B[p][q+1]);
                }
                if (TERMS == 2) {
                    uint32_t Al[4];
                    LDSM4(Al, Alo + aoff[t] + asw);
                    #pragma unroll
                    for (int n = 0; n < 4; n++) {
                        const int p = n >> 1, q = (n & 1) * 2;
                        MMA_FP16(acc[t][n], Al, B[p][q], B[p][q+1]);
                    }
                }
            }
        }
    }

    // epilogue
    const int rl = lane >> 2, cl2 = (lane & 3) * 2;
    #pragma unroll
    for (int t = 0; t < 4; t++)
        #pragma unroll
        for (int n = 0; n < 4; n++) {
            const int col = n0 + n0w + n*8 + cl2;
            #pragma unroll
            for (int half = 0; half < 2; half++) {
                const int row = m0 + m0w + t*16 + rl + half*8;
                float ox = (acc[t][n][half*2+0] + bias[col+0]) * scale;
                float oy = (acc[t][n][half*2+1] + bias[col+1]) * scale;
                if (is_qkv) {
                    const int hh = col >> 6, d0 = col & 63;
                    const int bb_ = row >> 10, ss_ = row & 1023;
                    size_t idx = ((size_t)((bb_*HH + hh)*SS + ss_))*DD + d0;
                    *(__half2*)(outH + idx) = __floats2half2_rn(ox, oy);
                } else {
                    float2 o; o.x = ox; o.y = oy;
                    *(float2*)(outp + (size_t)row * EE + col) = o;
                }
            }
        }
}

// ---------------------------------------------------------------------------
// Flash attention: S = Q·K (1-term, Q/K single fp16), O = (Phi+Plo)·V
// (V single fp16). CTA = 128 Q rows x (b,h). 8 warps, warp = m16 x n64.
// Smem: Q 16KB | 2 x 16KB KV stages | pk 4KB = 52KB.
// ---------------------------------------------------------------------------
__global__ void __launch_bounds__(256, 2) attn_mma_kernel(
    const int* __restrict__ pos_row, const int* __restrict__ pos_col,
    const float* __restrict__ rel_table)
{
    extern __shared__ char dsm[];
    const uint32_t sbase = smem_u32(dsm);
    const uint32_t sQ = sbase;
    int* pk = (int*)(dsm + 49152);

    const int tid = threadIdx.x;
    const int wid = tid >> 5, lane = tid & 31;
    const int l7 = lane & 7;
    const int rl = lane >> 2, cl2 = (lane & 3) * 2;
    const int achk = lane >> 4;
    const int bchk = (lane >> 3) & 1;

    const int q0 = blockIdx.x * 128;
    const int h = blockIdx.y, b = blockIdx.z;
    const size_t hb = (size_t)(b*HH + h) * SS * DD;

    #pragma unroll
    for (int i = 0; i < 4; i++) {
        int s = tid + i*256;
        pk[s] = (pos_row[b*SS + s] << 5) | pos_col[b*SS + s];
    }

    // Q stage: 128 rows x 64 fp16 = 16KB (4 chunks per thread)
    {
        const int r = tid & 127, hf = tid >> 7;
        const __half* src = g_Qh + hb + (size_t)(q0 + r)*DD;
        uint32_t dstrow = sQ + (uint32_t)r * 128u;
        #pragma unroll
        for (int j = 0; j < 4; j++) {
            int ch = hf*4 + j;
            CP_ASYNC16(dstrow + ((ch ^ (r & 7)) << 4), src + ch*8);
        }
        CP_COMMIT();
    }

    // KV stage: K 8KB + V 8KB = 16KB per stage
    auto kv_load = [&](int kb, int stg) {
        const int t = tid >> 7;
        const int r = tid & 63;
        const int hf = (tid >> 6) & 1;
        const __half* src = (t == 0 ? g_Kh : g_Vh) + hb + (size_t)(kb + r)*DD;
        uint32_t dstrow = sbase + 16384u + (uint32_t)stg*16384u
                        + (uint32_t)t*8192u + (uint32_t)r*128u;
        #pragma unroll
        for (int j = 0; j < 4; j++) {
            int ch = hf*4 + j;
            CP_ASYNC16(dstrow + ((ch ^ (r & 7)) << 4), src + ch*8);
        }
        CP_COMMIT();
    };
    kv_load(0, 0);

    CP_WAIT1();
    __syncthreads();

    // Q fragments (resident): 4 k-steps, single term
    uint32_t qh[4][4];
    const uint32_t aq = (uint32_t)(wid*16 + (lane & 15)) * 128u;
    #pragma unroll
    for (int ks = 0; ks < 4; ks++) {
        uint32_t sw = (uint32_t)((2*ks + achk) ^ l7) << 4;
        LDSM4(qh[ks], sQ + aq + sw);
    }

    const int rq0 = pk[q0 + wid*16 + rl];
    const int rq1 = pk[q0 + wid*16 + rl + 8];
    const float tb0 = rel_table[0*HH + h];
    const float tb1 = rel_table[1*HH + h];
    const float tb2 = rel_table[2*HH + h];
    const float tb3 = rel_table[3*HH + h];

    float oacc[8][4] = {};
    float m0 = -1e30f, m1 = -1e30f, l0 = 0.f, l1 = 0.f;

    #pragma unroll 1
    for (int kt = 0; kt < SS/64; kt++) {
        CP_WAIT0();
        __syncthreads();
        if (kt + 1 < SS/64) kv_load((kt + 1) * 64, (kt + 1) & 1);

        const uint32_t st = sbase + 16384u + (uint32_t)(kt & 1) * 16384u;
        const uint32_t Kt = st, Vt = st + 8192u;

        // S = Q K^T  (m16 x n64), fp32 accum, 1-term
        float sacc[8][4] = {};
        #pragma unroll
        for (int ks = 0; ks < 4; ks++) {
            const uint32_t bsw = (uint32_t)((2*ks + bchk) ^ l7) << 4;
            #pragma unroll
            for (int p = 0; p < 4; p++) {
                const uint32_t bo =
                    (uint32_t)(p*16 + l7 + ((lane >> 4) << 3)) * 128u + bsw;
                uint32_t B[4];
                LDSM4(B, Kt + bo);
                MMA_FP16(sacc[2*p],   qh[ks], B[0], B[1]);
                MMA_FP16(sacc[2*p+1], qh[ks], B[2], B[3]);
            }
        }

        // bias
        const int kb = kt * 64;
        #pragma unroll
        for (int t = 0; t < 8; t++) {
            int c0 = kb + t*8 + cl2;
            int rk0 = pk[c0], rk1 = pk[c0 + 1];
            int x;
            x = rq0 ^ rk0; sacc[t][0] += (x < 32) ? (((x & 31) == 0) ? tb3 : tb1)
                                                  : (((x & 31) == 0) ? tb2 : tb0);
            x = rq0 ^ rk1; sacc[t][1] += (x < 32) ? (((x & 31) == 0) ? tb3 : tb1)
                                                  : (((x & 31) == 0) ? tb2 : tb0);
            x = rq1 ^ rk0; sacc[t][2] += (x < 32) ? (((x & 31) == 0) ? tb3 : tb1)
                                                  : (((x & 31) == 0) ? tb2 : tb0);
            x = rq1 ^ rk1; sacc[t][3] += (x < 32) ? (((x & 31) == 0) ? tb3 : tb1)
                                                  : (((x & 31) == 0) ? tb2 : tb0);
        }

        // online softmax (MUFU exp; 4 lanes/row)
        float mx0 = sacc[0][0], mx1 = sacc[0][2];
        #pragma unroll
        for (int t = 0; t < 8; t++) {
            mx0 = fmaxf(mx0, fmaxf(sacc[t][0], sacc[t][1]));
            mx1 = fmaxf(mx1, fmaxf(sacc[t][2], sacc[t][3]));
        }
        mx0 = fmaxf(mx0, __shfl_xor_sync(0xffffffffu, mx0, 1));
        mx0 = fmaxf(mx0, __shfl_xor_sync(0xffffffffu, mx0, 2));
        mx1 = fmaxf(mx1, __shfl_xor_sync(0xffffffffu, mx1, 1));
        mx1 = fmaxf(mx1, __shfl_xor_sync(0xffffffffu, mx1, 2));
        float mn0 = fmaxf(m0, mx0), mn1 = fmaxf(m1, mx1);
        float sc0 = __expf(m0 - mn0), sc1 = __expf(m1 - mn1);
        m0 = mn0; m1 = mn1;
        float rs0 = 0.f, rs1 = 0.f;
        #pragma unroll
        for (int t = 0; t < 8; t++) {
            sacc[t][0] = __expf(sacc[t][0] - mn0);
            sacc[t][1] = __expf(sacc[t][1] - mn0);
            sacc[t][2] = __expf(sacc[t][2] - mn1);
            sacc[t][3] = __expf(sacc[t][3] - mn1);
            rs0 += sacc[t][0] + sacc[t][1];
            rs1 += sacc[t][2] + sacc[t][3];
        }
        rs0 += __shfl_xor_sync(0xffffffffu, rs0, 1);
        rs0 += __shfl_xor_sync(0xffffffffu, rs0, 2);
        rs1 += __shfl_xor_sync(0xffffffffu, rs1, 1);
        rs1 += __shfl_xor_sync(0xffffffffu, rs1, 2);
        l0 = l0 * sc0 + rs0;
        l1 = l1 * sc1 + rs1;
        #pragma unroll
        for (int t = 0; t < 8; t++) {
            oacc[t][0] *= sc0; oacc[t][1] *= sc0;
            oacc[t][2] *= sc1; oacc[t][3] *= sc1;
        }

        // O += (Phi+Plo) V : P hi/lo from sacc, V single fp16
        #pragma unroll
        for (int ks = 0; ks < 4; ks++) {
            uint32_t ph[4], pl[4];
            splitpack_h(sacc[2*ks][0],   sacc[2*ks][1],   ph[0], pl[0]);
            splitpack_h(sacc[2*ks][2],   sacc[2*ks][3],   ph[1], pl[1]);
            splitpack_h(sacc[2*ks+1][0], sacc[2*ks+1][1], ph[2], pl[2]);
            splitpack_h(sacc[2*ks+1][2], sacc[2*ks+1][3], ph[3], pl[3]);
            const uint32_t vr =
                (uint32_t)(ks*16 + l7 + (((lane >> 3) & 1) << 3)) * 128u;
            #pragma unroll
            for (int p = 0; p < 4; p++) {
                const uint32_t vsw = (uint32_t)((2*p + achk) ^ l7) << 4;
                uint32_t V[4];
                LDSM4T(V, Vt + vr + vsw);
                MMA_FP16(oacc[2*p],   ph, V[0], V[1]);
                MMA_FP16(oacc[2*p+1], ph, V[2], V[3]);
                MMA_FP16(oacc[2*p],   pl, V[0], V[1]);
                MMA_FP16(oacc[2*p+1], pl, V[2], V[3]);
            }
        }
    }

    // epilogue: normalize, emit fp16 hi/lo AO at [B,S,E] (e = h*64+d)
    const float inv0 = 1.0f / l0, inv1 = 1.0f / l1;
    const int qrow0 = q0 + wid*16 + rl;
    #pragma unroll
    for (int t = 0; t < 8; t++) {
        const int e = h*64 + t*8 + cl2;
        size_t i0 = (size_t)(b*SS + qrow0) * EE + e;
        size_t i1 = (size_t)(b*SS + qrow0 + 8) * EE + e;
        uint32_t hi, lo;
        splitpack_h(oacc[t][0] * inv0, oacc[t][1] * inv0, hi, lo);
        *(uint32_t*)(g_AOhi + i0) = hi;
        *(uint32_t*)(g_AOlo + i0) = lo;
        splitpack_h(oacc[t][2] * inv1, oacc[t][3] * inv1, hi, lo);
        *(uint32_t*)(g_AOhi + i1) = hi;
        *(uint32_t*)(g_AOlo + i1) = lo;
    }
}

// ---------------------------------------------------------------------------
extern "C" void kernel_launch(void* const* d_in, const int* in_sizes, int n_in,
                              void* d_out, int out_size) {
    const float* X  = (const float*)d_in[0];
    const int*   pr = (const int*)  d_in[1];
    const int*   pc = (const int*)  d_in[2];
    const float* qw = (const float*)d_in[3];
    const float* qb = (const float*)d_in[4];
    const float* kw = (const float*)d_in[5];
    const float* kb = (const float*)d_in[6];
    const float* vw = (const float*)d_in[7];
    const float* vb = (const float*)d_in[8];
    const float* ow = (const float*)d_in[9];
    const float* ob = (const float*)d_in[10];
    const float* rt = (const float*)d_in[11];
    float* out = (float*)d_out;

    const int DSMEM_G1 = 3 * 16384;   // 1-term: X + W per stage
    const int DSMEM_G2 = 3 * 24576;   // 2-term: AOhi + AOlo + W per stage
    cudaFuncSetAttribute(gemm_mma_kernel<1>,
                         cudaFuncAttributeMaxDynamicSharedMemorySize, DSMEM_G1);
    cudaFuncSetAttribute(gemm_mma_kernel<2>,
                         cudaFuncAttributeMaxDynamicSharedMemorySize, DSMEM_G2);
    const int DSMEM_A = 16384 + 2*16384 + 4096;    // 53248
    cudaFuncSetAttribute(attn_mma_kernel,
                         cudaFuncAttributeMaxDynamicSharedMemorySize, DSMEM_A);

    split_all_kernel<<<384 + 4*72, 256>>>(X, qw, kw, vw, ow);

    dim3 g1(EE/128, MT/128, 3);
    gemm_mma_kernel<1><<<g1, 256, DSMEM_G1>>>(qb, kb, vb, nullptr, 0, 1);

    dim3 g2(SS/128, HH, BB);
    attn_mma_kernel<<<g2, 256, DSMEM_A>>>(pr, pc, rt);

    dim3 g3(EE/128, MT/128, 1);
    gemm_mma_kernel<2><<<g3, 256, DSMEM_G2>>>(ob, ob, ob, out, 3, 0);
}

// round 14
// speedup vs baseline: 2.2584x; 1.1988x over previous
#include <cuda_runtime.h>
#include <cuda_bf16.h>
#include <cuda_fp16.h>
#include <cstdint>
#include <math.h>

#define BB 4
#define SS 1024
#define EE 768
#define HH 12
#define DD 64
#define MT (BB*SS)
#define SCALING 0.125f

// ---------------- device scratch (allocation-free rule) ----------------
__device__ __half g_Qh[BB*HH*SS*DD];      // Q: single fp16 (scaled)
__device__ __half g_Kh[BB*HH*SS*DD];      // K: single fp16
__device__ __half g_Vh[BB*HH*SS*DD];      // V: single fp16
__device__ __half g_Xh[MT*EE];            // X: single fp16
__device__ __half g_Wh[4*EE*EE];          // weights: single fp16
__device__ __half g_AOh[MT*EE];           // AO: single fp16

__device__ __forceinline__ uint32_t smem_u32(const void* p) {
    uint32_t a;
    asm("{ .reg .u64 t; cvta.to.shared.u64 t, %1; cvt.u32.u64 %0, t; }"
        : "=r"(a) : "l"(p));
    return a;
}

#define LDSM4(r, addr) \
    asm volatile("ldmatrix.sync.aligned.m8n8.x4.shared.b16 {%0,%1,%2,%3}, [%4];" \
        : "=r"((r)[0]), "=r"((r)[1]), "=r"((r)[2]), "=r"((r)[3]) : "r"(addr))
#define LDSM4T(r, addr) \
    asm volatile("ldmatrix.sync.aligned.m8n8.x4.trans.shared.b16 {%0,%1,%2,%3}, [%4];" \
        : "=r"((r)[0]), "=r"((r)[1]), "=r"((r)[2]), "=r"((r)[3]) : "r"(addr))

#define MMA_FP16(d, a, b0v, b1v) \
    asm volatile("mma.sync.aligned.m16n8k16.row.col.f32.f16.f16.f32 " \
        "{%0,%1,%2,%3}, {%4,%5,%6,%7}, {%8,%9}, {%0,%1,%2,%3};" \
        : "+f"((d)[0]), "+f"((d)[1]), "+f"((d)[2]), "+f"((d)[3]) \
        : "r"((a)[0]), "r"((a)[1]), "r"((a)[2]), "r"((a)[3]), "r"(b0v), "r"(b1v))

#define CP_ASYNC16(smem, gmem) \
    asm volatile("cp.async.cg.shared.global [%0], [%1], 16;" :: "r"(smem), "l"(gmem))
#define CP_COMMIT()  asm volatile("cp.async.commit_group;" ::: "memory")
#define CP_WAIT0()   asm volatile("cp.async.wait_group 0;" ::: "memory")
#define CP_WAIT1()   asm volatile("cp.async.wait_group 1;" ::: "memory")

// ---------------------------------------------------------------------------
// convert: blocks [0,384) = X -> single fp16; then 4x72 = W -> single fp16
// ---------------------------------------------------------------------------
__global__ void __launch_bounds__(256) split_all_kernel(
    const float* __restrict__ X,
    const float* __restrict__ qw, const float* __restrict__ kw,
    const float* __restrict__ vw, const float* __restrict__ ow)
{
    const int bid = blockIdx.x;
    const float* src;
    __half* dst;
    size_t off;
    if (bid < 384) {
        src = X; dst = g_Xh; off = (size_t)bid * 8192;
    } else {
        int r = bid - 384;
        int slot = r / 72, rb = r % 72;
        src = (slot == 0) ? qw : (slot == 1) ? kw : (slot == 2) ? vw : ow;
        dst = g_Wh + (size_t)slot * EE * EE;
        off = (size_t)rb * 8192;
    }
    float4 v[8];
    #pragma unroll
    for (int u = 0; u < 8; u++)
        v[u] = *(const float4*)(src + off + u*1024 + threadIdx.x*4);
    #pragma unroll
    for (int u = 0; u < 8; u++) {
        size_t i = off + u*1024 + threadIdx.x*4;
        __half2 a = __floats2half2_rn(v[u].x, v[u].y);
        __half2 b = __floats2half2_rn(v[u].z, v[u].w);
        *(__half2*)(dst + i)     = a;
        *(__half2*)(dst + i + 2) = b;
    }
}

// ---------------------------------------------------------------------------
// HMMA GEMM (1-term fp16): D = A(M,K) @ W(N,K)^T, fp32 accum.
// CTA 128x128, 8 warps (2x4), warp tile 64x32, BK=32, 3-stage cp.async.
// is_qkv=1: A = g_Xh; out = Q/K/V single fp16, [B,H,S,D], Q scaled.
// is_qkv=0: A = g_AOh; out = outp fp32 [M,E] (+bias).
// ---------------------------------------------------------------------------
#define NS (EE/32)       // 24 K-stages
#define STG_B 16384u     // A + W tiles per stage
__global__ void __launch_bounds__(256, 2) gemm_mma_kernel(
    const float* __restrict__ b0p, const float* __restrict__ b1p,
    const float* __restrict__ b2p, float* __restrict__ outp,
    int wslot0, int is_qkv)
{
    extern __shared__ char dsm[];
    const uint32_t sbase = smem_u32(dsm);

    const int tid = threadIdx.x;
    const int wid = tid >> 5, lane = tid & 31;
    const int warp_m = wid & 1, warp_n = wid >> 1;
    const int m0w = warp_m * 64, n0w = warp_n * 32;

    const int z = is_qkv ? blockIdx.z : 0;
    const size_t woff = (size_t)(wslot0 + z) * EE * EE;
    const float* bias = (z == 0) ? b0p : (z == 1) ? b1p : b2p;
    const float scale = (is_qkv && z == 0) ? SCALING : 1.0f;
    __half* outH = (z == 0) ? g_Qh : (z == 1) ? g_Kh : g_Vh;

    const int n0 = blockIdx.x * 128;
    const int m0 = blockIdx.y * 128;

    const __half* s0 = (is_qkv ? g_Xh : g_AOh) + (size_t)m0 * EE;
    const __half* s2 = g_Wh + woff + (size_t)n0 * EE;

    const int lrow = tid >> 2;
    const int lch  = tid & 3;
    auto stage_load = [&](int k0, int stg) {
        uint32_t sb = sbase + (uint32_t)stg * STG_B;
        #pragma unroll
        for (int t = 0; t < 2; t++) {
            const __half* sp = (t == 0 ? s0 : s2) + k0 + lch*8;
            uint32_t tb = sb + (uint32_t)t * 8192u;
            #pragma unroll
            for (int j = 0; j < 2; j++) {
                int row = lrow + j*64;
                CP_ASYNC16(tb + row*64 + ((lch ^ ((row >> 1) & 3)) << 4),
                           sp + (size_t)row * EE);
            }
        }
        CP_COMMIT();
    };

    const int arow_sw = (lane >> 1) & 3;
    const int brow7 = (lane & 7) + ((lane >> 4) << 3);
    const int brow_sw = (brow7 >> 1) & 3;
    uint32_t aoff[4], boff[2];
    #pragma unroll
    for (int t = 0; t < 4; t++)
        aoff[t] = (uint32_t)(m0w + t*16 + (lane & 15)) * 64u;
    #pragma unroll
    for (int p = 0; p < 2; p++)
        boff[p] = (uint32_t)(n0w + p*16 + brow7) * 64u;
    const int achk = lane >> 4;
    const int bchk = (lane >> 3) & 1;

    float acc[4][4][4] = {};

    stage_load(0, 0);
    stage_load(32, 1);

    #pragma unroll 1
    for (int s = 0; s < NS; s++) {
        if (s == NS - 1) { CP_WAIT0(); } else { CP_WAIT1(); }
        __syncthreads();
        if (s + 2 < NS) stage_load((s + 2) * 32, (s + 2) % 3);

        const uint32_t stg = sbase + (uint32_t)(s % 3) * STG_B;
        const uint32_t Ah_ = stg;
        const uint32_t Bh  = stg + 8192u;

        #pragma unroll
        for (int ks = 0; ks < 2; ks++) {
            const uint32_t asw = (uint32_t)((2*ks + achk) ^ arow_sw) << 4;
            const uint32_t bsw = (uint32_t)((2*ks + bchk) ^ brow_sw) << 4;
            uint32_t B[2][4];
            #pragma unroll
            for (int p = 0; p < 2; p++)
                LDSM4(B[p], Bh + boff[p] + bsw);
            #pragma unroll
            for (int t = 0; t < 4; t++) {
                uint32_t A[4];
                LDSM4(A, Ah_ + aoff[t] + asw);
                #pragma unroll
                for (int n = 0; n < 4; n++) {
                    const int p = n >> 1, q = (n & 1) * 2;
                    MMA_FP16(acc[t][n], A, B[p][q], B[p][q+1]);
                }
            }
        }
    }

    // epilogue
    const int rl = lane >> 2, cl2 = (lane & 3) * 2;
    #pragma unroll
    for (int t = 0; t < 4; t++)
        #pragma unroll
        for (int n = 0; n < 4; n++) {
            const int col = n0 + n0w + n*8 + cl2;
            #pragma unroll
            for (int half = 0; half < 2; half++) {
                const int row = m0 + m0w + t*16 + rl + half*8;
                float ox = (acc[t][n][half*2+0] + bias[col+0]) * scale;
                float oy = (acc[t][n][half*2+1] + bias[col+1]) * scale;
                if (is_qkv) {
                    const int hh = col >> 6, d0 = col & 63;
                    const int bb_ = row >> 10, ss_ = row & 1023;
                    size_t idx = ((size_t)((bb_*HH + hh)*SS + ss_))*DD + d0;
                    *(__half2*)(outH + idx) = __floats2half2_rn(ox, oy);
                } else {
                    float2 o; o.x = ox; o.y = oy;
                    *(float2*)(outp + (size_t)row * EE + col) = o;
                }
            }
        }
}

// ---------------------------------------------------------------------------
// Flash attention, all 1-term fp16: S = Q·K, O = P·V (Q/K/V/P single fp16,
// fp32 accumulate; error budget analysis in journal). CTA = 128 Q rows x
// (b,h). 8 warps, warp = m16 x n64. Smem: Q 16KB | 2 x 16KB KV | pk 4KB.
// ---------------------------------------------------------------------------
__global__ void __launch_bounds__(256, 2) attn_mma_kernel(
    const int* __restrict__ pos_row, const int* __restrict__ pos_col,
    const float* __restrict__ rel_table)
{
    extern __shared__ char dsm[];
    const uint32_t sbase = smem_u32(dsm);
    const uint32_t sQ = sbase;
    int* pk = (int*)(dsm + 49152);

    const int tid = threadIdx.x;
    const int wid = tid >> 5, lane = tid & 31;
    const int l7 = lane & 7;
    const int rl = lane >> 2, cl2 = (lane & 3) * 2;
    const int achk = lane >> 4;
    const int bchk = (lane >> 3) & 1;

    const int q0 = blockIdx.x * 128;
    const int h = blockIdx.y, b = blockIdx.z;
    const size_t hb = (size_t)(b*HH + h) * SS * DD;

    #pragma unroll
    for (int i = 0; i < 4; i++) {
        int s = tid + i*256;
        pk[s] = (pos_row[b*SS + s] << 5) | pos_col[b*SS + s];
    }

    // Q stage: 128 rows x 64 fp16 = 16KB
    {
        const int r = tid & 127, hf = tid >> 7;
        const __half* src = g_Qh + hb + (size_t)(q0 + r)*DD;
        uint32_t dstrow = sQ + (uint32_t)r * 128u;
        #pragma unroll
        for (int j = 0; j < 4; j++) {
            int ch = hf*4 + j;
            CP_ASYNC16(dstrow + ((ch ^ (r & 7)) << 4), src + ch*8);
        }
        CP_COMMIT();
    }

    // KV stage: K 8KB + V 8KB = 16KB per stage
    auto kv_load = [&](int kb, int stg) {
        const int t = tid >> 7;
        const int r = tid & 63;
        const int hf = (tid >> 6) & 1;
        const __half* src = (t == 0 ? g_Kh : g_Vh) + hb + (size_t)(kb + r)*DD;
        uint32_t dstrow = sbase + 16384u + (uint32_t)stg*16384u
                        + (uint32_t)t*8192u + (uint32_t)r*128u;
        #pragma unroll
        for (int j = 0; j < 4; j++) {
            int ch = hf*4 + j;
            CP_ASYNC16(dstrow + ((ch ^ (r & 7)) << 4), src + ch*8);
        }
        CP_COMMIT();
    };
    kv_load(0, 0);

    CP_WAIT1();
    __syncthreads();

    uint32_t qh[4][4];
    const uint32_t aq = (uint32_t)(wid*16 + (lane & 15)) * 128u;
    #pragma unroll
    for (int ks = 0; ks < 4; ks++) {
        uint32_t sw = (uint32_t)((2*ks + achk) ^ l7) << 4;
        LDSM4(qh[ks], sQ + aq + sw);
    }

    const int rq0 = pk[q0 + wid*16 + rl];
    const int rq1 = pk[q0 + wid*16 + rl + 8];
    const float tb0 = rel_table[0*HH + h];
    const float tb1 = rel_table[1*HH + h];
    const float tb2 = rel_table[2*HH + h];
    const float tb3 = rel_table[3*HH + h];

    float oacc[8][4] = {};
    float m0 = -1e30f, m1 = -1e30f, l0 = 0.f, l1 = 0.f;

    #pragma unroll 1
    for (int kt = 0; kt < SS/64; kt++) {
        CP_WAIT0();
        __syncthreads();
        if (kt + 1 < SS/64) kv_load((kt + 1) * 64, (kt + 1) & 1);

        const uint32_t st = sbase + 16384u + (uint32_t)(kt & 1) * 16384u;
        const uint32_t Kt = st, Vt = st + 8192u;

        // S = Q K^T  (m16 x n64), fp32 accum
        float sacc[8][4] = {};
        #pragma unroll
        for (int ks = 0; ks < 4; ks++) {
            const uint32_t bsw = (uint32_t)((2*ks + bchk) ^ l7) << 4;
            #pragma unroll
            for (int p = 0; p < 4; p++) {
                const uint32_t bo =
                    (uint32_t)(p*16 + l7 + ((lane >> 4) << 3)) * 128u + bsw;
                uint32_t B[4];
                LDSM4(B, Kt + bo);
                MMA_FP16(sacc[2*p],   qh[ks], B[0], B[1]);
                MMA_FP16(sacc[2*p+1], qh[ks], B[2], B[3]);
            }
        }

        // bias
        const int kb = kt * 64;
        #pragma unroll
        for (int t = 0; t < 8; t++) {
            int c0 = kb + t*8 + cl2;
            int rk0 = pk[c0], rk1 = pk[c0 + 1];
            int x;
            x = rq0 ^ rk0; sacc[t][0] += (x < 32) ? (((x & 31) == 0) ? tb3 : tb1)
                                                  : (((x & 31) == 0) ? tb2 : tb0);
            x = rq0 ^ rk1; sacc[t][1] += (x < 32) ? (((x & 31) == 0) ? tb3 : tb1)
                                                  : (((x & 31) == 0) ? tb2 : tb0);
            x = rq1 ^ rk0; sacc[t][2] += (x < 32) ? (((x & 31) == 0) ? tb3 : tb1)
                                                  : (((x & 31) == 0) ? tb2 : tb0);
            x = rq1 ^ rk1; sacc[t][3] += (x < 32) ? (((x & 31) == 0) ? tb3 : tb1)
                                                  : (((x & 31) == 0) ? tb2 : tb0);
        }

        // online softmax (MUFU exp; 4 lanes/row)
        float mx0 = sacc[0][0], mx1 = sacc[0][2];
        #pragma unroll
        for (int t = 0; t < 8; t++) {
            mx0 = fmaxf(mx0, fmaxf(sacc[t][0], sacc[t][1]));
            mx1 = fmaxf(mx1, fmaxf(sacc[t][2], sacc[t][3]));
        }
        mx0 = fmaxf(mx0, __shfl_xor_sync(0xffffffffu, mx0, 1));
        mx0 = fmaxf(mx0, __shfl_xor_sync(0xffffffffu, mx0, 2));
        mx1 = fmaxf(mx1, __shfl_xor_sync(0xffffffffu, mx1, 1));
        mx1 = fmaxf(mx1, __shfl_xor_sync(0xffffffffu, mx1, 2));
        float mn0 = fmaxf(m0, mx0), mn1 = fmaxf(m1, mx1);
        float sc0 = __expf(m0 - mn0), sc1 = __expf(m1 - mn1);
        m0 = mn0; m1 = mn1;
        float rs0 = 0.f, rs1 = 0.f;
        #pragma unroll
        for (int t = 0; t < 8; t++) {
            sacc[t][0] = __expf(sacc[t][0] - mn0);
            sacc[t][1] = __expf(sacc[t][1] - mn0);
            sacc[t][2] = __expf(sacc[t][2] - mn1);
            sacc[t][3] = __expf(sacc[t][3] - mn1);
            rs0 += sacc[t][0] + sacc[t][1];
            rs1 += sacc[t][2] + sacc[t][3];
        }
        rs0 += __shfl_xor_sync(0xffffffffu, rs0, 1);
        rs0 += __shfl_xor_sync(0xffffffffu, rs0, 2);
        rs1 += __shfl_xor_sync(0xffffffffu, rs1, 1);
        rs1 += __shfl_xor_sync(0xffffffffu, rs1, 2);
        l0 = l0 * sc0 + rs0;
        l1 = l1 * sc1 + rs1;
        #pragma unroll
        for (int t = 0; t < 8; t++) {
            oacc[t][0] *= sc0; oacc[t][1] *= sc0;
            oacc[t][2] *= sc1; oacc[t][3] *= sc1;
        }

        // O += P V : P single fp16 from sacc
        #pragma unroll
        for (int ks = 0; ks < 4; ks++) {
            uint32_t ph[4];
            __half2 h2;
            h2 = __floats2half2_rn(sacc[2*ks][0],   sacc[2*ks][1]);   ph[0] = *(uint32_t*)&h2;
            h2 = __floats2half2_rn(sacc[2*ks][2],   sacc[2*ks][3]);   ph[1] = *(uint32_t*)&h2;
            h2 = __floats2half2_rn(sacc[2*ks+1][0], sacc[2*ks+1][1]); ph[2] = *(uint32_t*)&h2;
            h2 = __floats2half2_rn(sacc[2*ks+1][2], sacc[2*ks+1][3]); ph[3] = *(uint32_t*)&h2;
            const uint32_t vr =
                (uint32_t)(ks*16 + l7 + (((lane >> 3) & 1) << 3)) * 128u;
            #pragma unroll
            for (int p = 0; p < 4; p++) {
                const uint32_t vsw = (uint32_t)((2*p + achk) ^ l7) << 4;
                uint32_t V[4];
                LDSM4T(V, Vt + vr + vsw);
                MMA_FP16(oacc[2*p],   ph, V[0], V[1]);
                MMA_FP16(oacc[2*p+1], ph, V[2], V[3]);
            }
        }
    }

    // epilogue: normalize, emit single fp16 AO at [B,S,E] (e = h*64+d)
    const float inv0 = 1.0f / l0, inv1 = 1.0f / l1;
    const int qrow0 = q0 + wid*16 + rl;
    #pragma unroll
    for (int t = 0; t < 8; t++) {
        const int e = h*64 + t*8 + cl2;
        size_t i0 = (size_t)(b*SS + qrow0) * EE + e;
        size_t i1 = (size_t)(b*SS + qrow0 + 8) * EE + e;
        *(__half2*)(g_AOh + i0) = __floats2half2_rn(oacc[t][0]*inv0, oacc[t][1]*inv0);
        *(__half2*)(g_AOh + i1) = __floats2half2_rn(oacc[t][2]*inv1, oacc[t][3]*inv1);
    }
}

// ---------------------------------------------------------------------------
extern "C" void kernel_launch(void* const* d_in, const int* in_sizes, int n_in,
                              void* d_out, int out_size) {
    const float* X  = (const float*)d_in[0];
    const int*   pr = (const int*)  d_in[1];
    const int*   pc = (const int*)  d_in[2];
    const float* qw = (const float*)d_in[3];
    const float* qb = (const float*)d_in[4];
    const float* kw = (const float*)d_in[5];
    const float* kb = (const float*)d_in[6];
    const float* vw = (const float*)d_in[7];
    const float* vb = (const float*)d_in[8];
    const float* ow = (const float*)d_in[9];
    const float* ob = (const float*)d_in[10];
    const float* rt = (const float*)d_in[11];
    float* out = (float*)d_out;

    const int DSMEM_G = 3 * 16384;                 // 3-stage, 16KB/stage
    cudaFuncSetAttribute(gemm_mma_kernel,
                         cudaFuncAttributeMaxDynamicSharedMemorySize, DSMEM_G);
    const int DSMEM_A = 16384 + 2*16384 + 4096;    // 53248
    cudaFuncSetAttribute(attn_mma_kernel,
                         cudaFuncAttributeMaxDynamicSharedMemorySize, DSMEM_A);

    split_all_kernel<<<384 + 4*72, 256>>>(X, qw, kw, vw, ow);

    dim3 g1(EE/128, MT/128, 3);
    gemm_mma_kernel<<<g1, 256, DSMEM_G>>>(qb, kb, vb, nullptr, 0, 1);

    dim3 g2(SS/128, HH, BB);
    attn_mma_kernel<<<g2, 256, DSMEM_A>>>(pr, pc, rt);

    dim3 g3(EE/128, MT/128, 1);
    gemm_mma_kernel<<<g3, 256, DSMEM_G>>>(ob, ob, ob, out, 3, 0);
}